// round 1
// baseline (speedup 1.0000x reference)
#include <cuda_runtime.h>
#include <math.h>

#define D_EMB   1024
#define N_BATCH 4
#define N_SEQ   2048
#define BN_TOT  (N_BATCH * N_SEQ)   // 8192

// Scratch (device globals -- allocation-free per harness rules)
__device__ float g_Q[BN_TOT * D_EMB];
__device__ float g_K[BN_TOT * D_EMB];
__device__ float g_V[BN_TOT * D_EMB];
__device__ float g_S[N_BATCH * N_SEQ * N_SEQ];
__device__ float g_T[BN_TOT * D_EMB];

// ---------------------------------------------------------------------------
// Generic 128x128x16 fp32 SGEMM, 256 threads, 8x8 per-thread microtile.
// A: [M,K] row-major. B: NN -> [K,N] row-major; NT -> [N,K] row-major.
// Batched via blockIdx.z with element strides sA/sB/sC.
// All of M,N multiples of 128 and K multiple of 16 (true for every call here).
// ---------------------------------------------------------------------------
template <bool TRANSB, bool BIAS, bool RELU>
__global__ __launch_bounds__(256)
void sgemm128(const float* __restrict__ Aall, const float* __restrict__ Ball,
              const float* __restrict__ bias, float* __restrict__ Call,
              int M, int N, int K,
              long long sA, long long sB, long long sC)
{
    const float* A = Aall + (long long)blockIdx.z * sA;
    const float* B = Ball + (long long)blockIdx.z * sB;
    float*       C = Call + (long long)blockIdx.z * sC;

    __shared__ float As[16][128];
    __shared__ float Bs[16][128];

    const int tid  = threadIdx.x;
    const int row0 = blockIdx.y * 128;
    const int col0 = blockIdx.x * 128;

    const int trow = (tid >> 4) << 3;   // (tid/16)*8
    const int tcol = (tid & 15) << 3;   // (tid%16)*8

    float acc[8][8];
#pragma unroll
    for (int i = 0; i < 8; i++)
#pragma unroll
        for (int j = 0; j < 8; j++) acc[i][j] = 0.f;

    for (int k0 = 0; k0 < K; k0 += 16) {
        // ---- global loads into registers (before smem handoff) ----
        float4 areg[2], breg[2];
#pragma unroll
        for (int i = 0; i < 2; i++) {
            int idx = tid + i * 256;
            int r = idx >> 2, c4 = idx & 3;
            areg[i] = *(const float4*)(A + (long long)(row0 + r) * K + k0 + c4 * 4);
        }
        if (TRANSB) {
#pragma unroll
            for (int i = 0; i < 2; i++) {
                int idx = tid + i * 256;
                int n = idx >> 2, c4 = idx & 3;
                breg[i] = *(const float4*)(B + (long long)(col0 + n) * K + k0 + c4 * 4);
            }
        } else {
#pragma unroll
            for (int i = 0; i < 2; i++) {
                int idx = tid + i * 256;
                int r = idx >> 5, c4 = idx & 31;
                breg[i] = *(const float4*)(B + (long long)(k0 + r) * N + col0 + c4 * 4);
            }
        }

        __syncthreads();   // previous iteration's compute done
        // ---- smem stores ----
#pragma unroll
        for (int i = 0; i < 2; i++) {
            int idx = tid + i * 256;
            int r = idx >> 2, c4 = idx & 3;
            As[c4 * 4 + 0][r] = areg[i].x;
            As[c4 * 4 + 1][r] = areg[i].y;
            As[c4 * 4 + 2][r] = areg[i].z;
            As[c4 * 4 + 3][r] = areg[i].w;
        }
        if (TRANSB) {
#pragma unroll
            for (int i = 0; i < 2; i++) {
                int idx = tid + i * 256;
                int n = idx >> 2, c4 = idx & 3;
                Bs[c4 * 4 + 0][n] = breg[i].x;
                Bs[c4 * 4 + 1][n] = breg[i].y;
                Bs[c4 * 4 + 2][n] = breg[i].z;
                Bs[c4 * 4 + 3][n] = breg[i].w;
            }
        } else {
#pragma unroll
            for (int i = 0; i < 2; i++) {
                int idx = tid + i * 256;
                int r = idx >> 5, c4 = idx & 31;
                *(float4*)&Bs[r][c4 * 4] = breg[i];
            }
        }
        __syncthreads();

        // ---- compute ----
#pragma unroll
        for (int kk = 0; kk < 16; kk++) {
            float a[8], b[8];
            *(float4*)(a)     = *(const float4*)&As[kk][trow];
            *(float4*)(a + 4) = *(const float4*)&As[kk][trow + 4];
            *(float4*)(b)     = *(const float4*)&Bs[kk][tcol];
            *(float4*)(b + 4) = *(const float4*)&Bs[kk][tcol + 4];
#pragma unroll
            for (int i = 0; i < 8; i++)
#pragma unroll
                for (int j = 0; j < 8; j++)
                    acc[i][j] = fmaf(a[i], b[j], acc[i][j]);
        }
    }

    // ---- epilogue ----
#pragma unroll
    for (int i = 0; i < 8; i++) {
        long long crow = (long long)(row0 + trow + i);
#pragma unroll
        for (int j = 0; j < 8; j += 4) {
            float4 v;
            v.x = acc[i][j + 0]; v.y = acc[i][j + 1];
            v.z = acc[i][j + 2]; v.w = acc[i][j + 3];
            if (BIAS) {
                const float4 bv = *(const float4*)(bias + col0 + tcol + j);
                v.x += bv.x; v.y += bv.y; v.z += bv.z; v.w += bv.w;
            }
            if (RELU) {
                v.x = fmaxf(v.x, 0.f); v.y = fmaxf(v.y, 0.f);
                v.z = fmaxf(v.z, 0.f); v.w = fmaxf(v.w, 0.f);
            }
            *(float4*)(C + crow * N + col0 + tcol + j) = v;
        }
    }
}

// ---------------------------------------------------------------------------
// Row softmax over 2048 elements. One block (256 threads) per row.
// ---------------------------------------------------------------------------
__inline__ __device__ float warpMax(float v) {
#pragma unroll
    for (int o = 16; o > 0; o >>= 1) v = fmaxf(v, __shfl_xor_sync(0xffffffffu, v, o));
    return v;
}
__inline__ __device__ float warpSum(float v) {
#pragma unroll
    for (int o = 16; o > 0; o >>= 1) v += __shfl_xor_sync(0xffffffffu, v, o);
    return v;
}

__global__ __launch_bounds__(256)
void softmax_rows_2048(float* __restrict__ S)
{
    float* row = S + (long long)blockIdx.x * N_SEQ;
    const int tid  = threadIdx.x;
    const int lane = tid & 31;
    const int wid  = tid >> 5;

    float4 v0 = ((const float4*)row)[tid];
    float4 v1 = ((const float4*)row)[tid + 256];

    __shared__ float sm[8];

    // max
    float m = fmaxf(fmaxf(fmaxf(v0.x, v0.y), fmaxf(v0.z, v0.w)),
                    fmaxf(fmaxf(v1.x, v1.y), fmaxf(v1.z, v1.w)));
    m = warpMax(m);
    if (lane == 0) sm[wid] = m;
    __syncthreads();
    if (wid == 0) {
        float t = (lane < 8) ? sm[lane] : -3.402823e38f;
        t = warpMax(t);
        if (lane == 0) sm[0] = t;
    }
    __syncthreads();
    m = sm[0];
    __syncthreads();   // protect sm before reuse

    // exp + sum
    v0.x = expf(v0.x - m); v0.y = expf(v0.y - m);
    v0.z = expf(v0.z - m); v0.w = expf(v0.w - m);
    v1.x = expf(v1.x - m); v1.y = expf(v1.y - m);
    v1.z = expf(v1.z - m); v1.w = expf(v1.w - m);

    float s = (v0.x + v0.y + v0.z + v0.w) + (v1.x + v1.y + v1.z + v1.w);
    s = warpSum(s);
    if (lane == 0) sm[wid] = s;
    __syncthreads();
    if (wid == 0) {
        float t = (lane < 8) ? sm[lane] : 0.f;
        t = warpSum(t);
        if (lane == 0) sm[0] = t;
    }
    __syncthreads();
    const float inv = 1.0f / sm[0];

    v0.x *= inv; v0.y *= inv; v0.z *= inv; v0.w *= inv;
    v1.x *= inv; v1.y *= inv; v1.z *= inv; v1.w *= inv;
    ((float4*)row)[tid]       = v0;
    ((float4*)row)[tid + 256] = v1;
}

// ---------------------------------------------------------------------------
extern "C" void kernel_launch(void* const* d_in, const int* in_sizes, int n_in,
                              void* d_out, int out_size)
{
    const float* x  = (const float*)d_in[0];
    const float* Wq = (const float*)d_in[1];
    const float* bq = (const float*)d_in[2];
    const float* Wk = (const float*)d_in[3];
    const float* bk = (const float*)d_in[4];
    const float* Wv = (const float*)d_in[5];
    const float* bv = (const float*)d_in[6];
    const float* Wm = (const float*)d_in[7];
    const float* bm = (const float*)d_in[8];
    float* out = (float*)d_out;

    float *Q, *K, *V, *S, *T;
    cudaGetSymbolAddress((void**)&Q, g_Q);
    cudaGetSymbolAddress((void**)&K, g_K);
    cudaGetSymbolAddress((void**)&V, g_V);
    cudaGetSymbolAddress((void**)&S, g_S);
    cudaGetSymbolAddress((void**)&T, g_T);

    const dim3 blk(256);

    // 1) Projections: [8192,1024] = x @ W + b
    {
        dim3 grid(D_EMB / 128, BN_TOT / 128, 1);
        sgemm128<false, true, false><<<grid, blk>>>(x, Wq, bq, Q, BN_TOT, D_EMB, D_EMB, 0, 0, 0);
        sgemm128<false, true, false><<<grid, blk>>>(x, Wk, bk, K, BN_TOT, D_EMB, D_EMB, 0, 0, 0);
        sgemm128<false, true, false><<<grid, blk>>>(x, Wv, bv, V, BN_TOT, D_EMB, D_EMB, 0, 0, 0);
    }

    // 2) S'[b,j,i] = K_b @ Q_b^T   (NT gemm, batched over z)
    {
        dim3 grid(N_SEQ / 128, N_SEQ / 128, N_BATCH);
        sgemm128<true, false, false><<<grid, blk>>>(
            K, Q, nullptr, S, N_SEQ, N_SEQ, D_EMB,
            (long long)N_SEQ * D_EMB, (long long)N_SEQ * D_EMB,
            (long long)N_SEQ * N_SEQ);
    }

    // 3) Row softmax over i (last dim of S')
    softmax_rows_2048<<<BN_TOT, blk>>>(S);

    // 4) T[b] = softmax(S'_b) @ V_b   (NN gemm, batched)
    {
        dim3 grid(D_EMB / 128, N_SEQ / 128, N_BATCH);
        sgemm128<false, false, false><<<grid, blk>>>(
            S, V, nullptr, T, N_SEQ, D_EMB, N_SEQ,
            (long long)N_SEQ * N_SEQ, (long long)N_SEQ * D_EMB,
            (long long)N_SEQ * D_EMB);
    }

    // 5) out = relu(T @ Wm + bm)
    {
        dim3 grid(D_EMB / 128, BN_TOT / 128, 1);
        sgemm128<false, true, true><<<grid, blk>>>(T, Wm, bm, out, BN_TOT, D_EMB, D_EMB, 0, 0, 0);
    }
}

// round 3
// speedup vs baseline: 2.2714x; 2.2714x over previous
#include <cuda_runtime.h>
#include <cuda_bf16.h>
#include <stdint.h>
#include <math.h>

#define D_EMB   1024
#define N_BATCH 4
#define N_SEQ   2048
#define BN_TOT  (N_BATCH * N_SEQ)   // 8192

// ---------------------------------------------------------------------------
// Device scratch (allocation-free per harness rules)
// ---------------------------------------------------------------------------
__device__ __nv_bfloat16 g_xh[BN_TOT * D_EMB], g_xl[BN_TOT * D_EMB];
__device__ __nv_bfloat16 g_Wqh[D_EMB * D_EMB], g_Wql[D_EMB * D_EMB];
__device__ __nv_bfloat16 g_Wkh[D_EMB * D_EMB], g_Wkl[D_EMB * D_EMB];
__device__ __nv_bfloat16 g_Wvh[D_EMB * D_EMB], g_Wvl[D_EMB * D_EMB];
__device__ __nv_bfloat16 g_Wmh[D_EMB * D_EMB], g_Wml[D_EMB * D_EMB];
__device__ float g_Qf[BN_TOT * D_EMB];
__device__ float g_Kf[BN_TOT * D_EMB];
__device__ float g_Vf[BN_TOT * D_EMB];
__device__ float g_Tf[BN_TOT * D_EMB];
__device__ __nv_bfloat16 g_Qh[BN_TOT * D_EMB], g_Ql[BN_TOT * D_EMB];
__device__ __nv_bfloat16 g_Kh[BN_TOT * D_EMB], g_Kl[BN_TOT * D_EMB];
__device__ __nv_bfloat16 g_Vth[BN_TOT * D_EMB], g_Vtl[BN_TOT * D_EMB];
__device__ __nv_bfloat16 g_Th[BN_TOT * D_EMB], g_Tl[BN_TOT * D_EMB];
__device__ float g_S[(size_t)N_BATCH * N_SEQ * N_SEQ];
__device__ __nv_bfloat16 g_ah[(size_t)N_BATCH * N_SEQ * N_SEQ];
__device__ __nv_bfloat16 g_al[(size_t)N_BATCH * N_SEQ * N_SEQ];

// ---------------------------------------------------------------------------
// helpers
// ---------------------------------------------------------------------------
__device__ __forceinline__ uint32_t smem_u32(const void* p) {
    uint32_t a;
    asm("{ .reg .u64 t; cvta.to.shared.u64 t, %1; cvt.u32.u64 %0, t; }"
        : "=r"(a) : "l"(p));
    return a;
}
__device__ __forceinline__ uint64_t gptr64(const void* p) {
    uint64_t g;
    asm("cvta.to.global.u64 %0, %1;" : "=l"(g) : "l"(p));
    return g;
}
__device__ __forceinline__ void cp16(uint32_t saddr, const void* g) {
    asm volatile("cp.async.cg.shared.global [%0], [%1], 16;"
                 :: "r"(saddr), "l"(gptr64(g)) : "memory");
}

// warp-level bf16 MMA, fp32 accumulate (portable PTX -> fallback HMMA on sm_103)
__device__ __forceinline__ void mma16816(float* c, const uint32_t* a, const uint32_t* b) {
    asm volatile(
        "mma.sync.aligned.m16n8k16.row.col.f32.bf16.bf16.f32 "
        "{%0,%1,%2,%3}, {%4,%5,%6,%7}, {%8,%9}, {%0,%1,%2,%3};"
        : "+f"(c[0]), "+f"(c[1]), "+f"(c[2]), "+f"(c[3])
        : "r"(a[0]), "r"(a[1]), "r"(a[2]), "r"(a[3]), "r"(b[0]), "r"(b[1]));
}

// smem geometry: rows padded to 40 bf16 (80B) -> conflict-free fragment loads
#define KC          32
#define ROW_PAD     40
#define TILE_ELEMS  (128 * ROW_PAD)              // per matrix tile, bf16 elems
#define STAGE_BYTES (4 * TILE_ELEMS * 2)         // Ah|Al|Bh|Bl = 40960 B
#define N_STAGES    3
#define SMEM_BYTES  (N_STAGES * STAGE_BYTES)     // 122880 B

// ---------------------------------------------------------------------------
// NT GEMM: C[M,N] = (Ah+Al)[M,K] @ (Bh+Bl)[N,K]^T, 3-product bf16 split.
// CTA 128x128, 8 warps (2x4), warp tile 64x32, 3-stage cp.async pipeline.
// M,N multiples of 128; K multiple of 32.
// ---------------------------------------------------------------------------
template <bool BIAS, bool RELU>
__global__ __launch_bounds__(256, 1)
void gemm_mma(const __nv_bfloat16* __restrict__ Ah, const __nv_bfloat16* __restrict__ Al,
              const __nv_bfloat16* __restrict__ Bh, const __nv_bfloat16* __restrict__ Bl,
              const float* __restrict__ bias, float* __restrict__ C,
              int Nn, int Kd, long long sA, long long sB, long long sC)
{
    extern __shared__ __align__(128) char smem[];
    const int tid = threadIdx.x;
    const long long z = blockIdx.z;
    Ah += z * sA; Al += z * sA;
    Bh += z * sB; Bl += z * sB;
    C  += z * sC;
    const int row0 = blockIdx.y * 128;
    const int col0 = blockIdx.x * 128;

    const int warp  = tid >> 5;
    const int lane  = tid & 31;
    const int g     = lane >> 2;          // group row
    const int t     = lane & 3;           // thread-in-group
    const int mbase = (warp & 1) * 64;
    const int nbase = (warp >> 1) * 32;

    const uint32_t sbase = smem_u32(smem);

    float acc[4][4][4];
#pragma unroll
    for (int mi = 0; mi < 4; mi++)
#pragma unroll
        for (int ni = 0; ni < 4; ni++)
#pragma unroll
            for (int r = 0; r < 4; r++) acc[mi][ni][r] = 0.f;

    // ---- stage loader: 2048 x 16B cp.async per stage (8 per thread) ----
    auto load_stage = [&](int st, int kc) {
        const uint32_t sb = sbase + (uint32_t)st * STAGE_BYTES;
        const int k0 = kc * KC;
#pragma unroll
        for (int i = 0; i < 2; i++) {
            const int idx = tid + (i << 8);         // 0..511
            const int r  = idx >> 2;
            const int c4 = idx & 3;
            const uint32_t soff = (uint32_t)(r * 80 + c4 * 16);
            const long long ga = (long long)(row0 + r) * Kd + k0 + c4 * 8;
            const long long gb = (long long)(col0 + r) * Kd + k0 + c4 * 8;
            cp16(sb + soff,                     Ah + ga);
            cp16(sb + 1 * 10240 + soff,         Al + ga);
            cp16(sb + 2 * 10240 + soff,         Bh + gb);
            cp16(sb + 3 * 10240 + soff,         Bl + gb);
        }
        asm volatile("cp.async.commit_group;" ::: "memory");
    };

    // ---- stage compute: 2 k16 steps ----
    auto compute_stage = [&](int st) {
        const __nv_bfloat16* sAh = (const __nv_bfloat16*)(smem + (size_t)st * STAGE_BYTES);
        const __nv_bfloat16* sAl = sAh + TILE_ELEMS;
        const __nv_bfloat16* sBh = sAh + 2 * TILE_ELEMS;
        const __nv_bfloat16* sBl = sAh + 3 * TILE_ELEMS;
#pragma unroll
        for (int kk = 0; kk < KC; kk += 16) {
            uint32_t ahf[4][4], alf[4][4], bhf[4][2], blf[4][2];
            const int c0 = kk + t * 2;
#pragma unroll
            for (int mi = 0; mi < 4; mi++) {
                const int r0 = (mbase + mi * 16 + g) * ROW_PAD;
                ahf[mi][0] = *(const uint32_t*)&sAh[r0 + c0];
                ahf[mi][1] = *(const uint32_t*)&sAh[r0 + 8 * ROW_PAD + c0];
                ahf[mi][2] = *(const uint32_t*)&sAh[r0 + c0 + 8];
                ahf[mi][3] = *(const uint32_t*)&sAh[r0 + 8 * ROW_PAD + c0 + 8];
                alf[mi][0] = *(const uint32_t*)&sAl[r0 + c0];
                alf[mi][1] = *(const uint32_t*)&sAl[r0 + 8 * ROW_PAD + c0];
                alf[mi][2] = *(const uint32_t*)&sAl[r0 + c0 + 8];
                alf[mi][3] = *(const uint32_t*)&sAl[r0 + 8 * ROW_PAD + c0 + 8];
            }
#pragma unroll
            for (int ni = 0; ni < 4; ni++) {
                const int rn = (nbase + ni * 8 + g) * ROW_PAD;
                bhf[ni][0] = *(const uint32_t*)&sBh[rn + c0];
                bhf[ni][1] = *(const uint32_t*)&sBh[rn + c0 + 8];
                blf[ni][0] = *(const uint32_t*)&sBl[rn + c0];
                blf[ni][1] = *(const uint32_t*)&sBl[rn + c0 + 8];
            }
#pragma unroll
            for (int mi = 0; mi < 4; mi++)
#pragma unroll
                for (int ni = 0; ni < 4; ni++) {
                    mma16816(acc[mi][ni], ahf[mi], bhf[ni]);
                    mma16816(acc[mi][ni], ahf[mi], blf[ni]);
                    mma16816(acc[mi][ni], alf[mi], bhf[ni]);
                }
        }
    };

    const int nc = Kd / KC;      // >= 32 for all shapes here
    load_stage(0, 0);
    load_stage(1, 1);

    for (int c = 0; c < nc; c++) {
        if (c + 2 < nc) asm volatile("cp.async.wait_group 1;" ::: "memory");
        else            asm volatile("cp.async.wait_group 0;" ::: "memory");
        __syncthreads();
        compute_stage(c % N_STAGES);
        if (c + 2 < nc) load_stage((c + 2) % N_STAGES, c + 2);
    }

    // ---- epilogue ----
#pragma unroll
    for (int mi = 0; mi < 4; mi++) {
        const long long r = row0 + mbase + mi * 16 + g;
#pragma unroll
        for (int ni = 0; ni < 4; ni++) {
            const int cc = col0 + nbase + ni * 8 + t * 2;
            float2 v0, v1;
            v0.x = acc[mi][ni][0]; v0.y = acc[mi][ni][1];
            v1.x = acc[mi][ni][2]; v1.y = acc[mi][ni][3];
            if (BIAS) {
                const float2 bv = *(const float2*)(bias + cc);
                v0.x += bv.x; v0.y += bv.y;
                v1.x += bv.x; v1.y += bv.y;
            }
            if (RELU) {
                v0.x = fmaxf(v0.x, 0.f); v0.y = fmaxf(v0.y, 0.f);
                v1.x = fmaxf(v1.x, 0.f); v1.y = fmaxf(v1.y, 0.f);
            }
            *(float2*)(C + r * Nn + cc)       = v0;
            *(float2*)(C + (r + 8) * Nn + cc) = v1;
        }
    }
}

// ---------------------------------------------------------------------------
// fp32 -> (bf16 hi, bf16 lo) elementwise split
// ---------------------------------------------------------------------------
__device__ __forceinline__ void split1(float v, __nv_bfloat16& h, __nv_bfloat16& l) {
    h = __float2bfloat16(v);
    l = __float2bfloat16(v - __bfloat162float(h));
}
__device__ __forceinline__ uint32_t pack2(__nv_bfloat16 a, __nv_bfloat16 b) {
    __nv_bfloat162 t; t.x = a; t.y = b;
    return *reinterpret_cast<uint32_t*>(&t);
}

__global__ __launch_bounds__(256)
void split_kernel(const float* __restrict__ in, __nv_bfloat16* __restrict__ oh,
                  __nv_bfloat16* __restrict__ ol, long long n4)
{
    long long i = (long long)blockIdx.x * blockDim.x + threadIdx.x;
    if (i >= n4) return;
    float4 v = ((const float4*)in)[i];
    __nv_bfloat16 h0, h1, h2, h3, l0, l1, l2, l3;
    split1(v.x, h0, l0); split1(v.y, h1, l1);
    split1(v.z, h2, l2); split1(v.w, h3, l3);
    uint2 hv, lv;
    hv.x = pack2(h0, h1); hv.y = pack2(h2, h3);
    lv.x = pack2(l0, l1); lv.y = pack2(l2, l3);
    ((uint2*)oh)[i] = hv;
    ((uint2*)ol)[i] = lv;
}

// ---------------------------------------------------------------------------
// fp32 [R,C] -> transposed bf16 hi/lo [C,R] (batched via blockIdx.z)
// ---------------------------------------------------------------------------
__global__ __launch_bounds__(256)
void tsplit_kernel(const float* __restrict__ in, __nv_bfloat16* __restrict__ oh,
                   __nv_bfloat16* __restrict__ ol, int R, int C)
{
    __shared__ float t[32][33];
    const long long zoff = (long long)blockIdx.z * R * C;
    in += zoff; oh += zoff; ol += zoff;
    const int tx = threadIdx.x, ty = threadIdx.y;
    const int x = blockIdx.x * 32 + tx;
    const int y0 = blockIdx.y * 32 + ty;
#pragma unroll
    for (int i = 0; i < 32; i += 8)
        t[ty + i][tx] = in[(long long)(y0 + i) * C + x];
    __syncthreads();
    const int ox = blockIdx.y * 32 + tx;
    const int oy0 = blockIdx.x * 32 + ty;
#pragma unroll
    for (int i = 0; i < 32; i += 8) {
        float v = t[tx][ty + i];
        __nv_bfloat16 h, l;
        split1(v, h, l);
        oh[(long long)(oy0 + i) * R + ox] = h;
        ol[(long long)(oy0 + i) * R + ox] = l;
    }
}

// ---------------------------------------------------------------------------
// Row softmax over 2048 fp32 -> bf16 hi/lo outputs
// ---------------------------------------------------------------------------
__inline__ __device__ float warpMax(float v) {
#pragma unroll
    for (int o = 16; o > 0; o >>= 1) v = fmaxf(v, __shfl_xor_sync(0xffffffffu, v, o));
    return v;
}
__inline__ __device__ float warpSum(float v) {
#pragma unroll
    for (int o = 16; o > 0; o >>= 1) v += __shfl_xor_sync(0xffffffffu, v, o);
    return v;
}

__global__ __launch_bounds__(256)
void softmax_split(const float* __restrict__ S, __nv_bfloat16* __restrict__ ah,
                   __nv_bfloat16* __restrict__ al)
{
    const long long base = (long long)blockIdx.x * N_SEQ;
    const float* row = S + base;
    const int tid = threadIdx.x;
    const int lane = tid & 31;
    const int wid = tid >> 5;

    float4 v0 = ((const float4*)row)[tid];
    float4 v1 = ((const float4*)row)[tid + 256];

    __shared__ float sm[8];
    float m = fmaxf(fmaxf(fmaxf(v0.x, v0.y), fmaxf(v0.z, v0.w)),
                    fmaxf(fmaxf(v1.x, v1.y), fmaxf(v1.z, v1.w)));
    m = warpMax(m);
    if (lane == 0) sm[wid] = m;
    __syncthreads();
    if (wid == 0) {
        float t = (lane < 8) ? sm[lane] : -3.402823e38f;
        t = warpMax(t);
        if (lane == 0) sm[0] = t;
    }
    __syncthreads();
    m = sm[0];
    __syncthreads();

    v0.x = expf(v0.x - m); v0.y = expf(v0.y - m);
    v0.z = expf(v0.z - m); v0.w = expf(v0.w - m);
    v1.x = expf(v1.x - m); v1.y = expf(v1.y - m);
    v1.z = expf(v1.z - m); v1.w = expf(v1.w - m);

    float s = (v0.x + v0.y + v0.z + v0.w) + (v1.x + v1.y + v1.z + v1.w);
    s = warpSum(s);
    if (lane == 0) sm[wid] = s;
    __syncthreads();
    if (wid == 0) {
        float t = (lane < 8) ? sm[lane] : 0.f;
        t = warpSum(t);
        if (lane == 0) sm[0] = t;
    }
    __syncthreads();
    const float inv = 1.0f / sm[0];

    __nv_bfloat16 h0, h1, h2, h3, l0, l1, l2, l3;
    uint2 hv, lv;
    split1(v0.x * inv, h0, l0); split1(v0.y * inv, h1, l1);
    split1(v0.z * inv, h2, l2); split1(v0.w * inv, h3, l3);
    hv.x = pack2(h0, h1); hv.y = pack2(h2, h3);
    lv.x = pack2(l0, l1); lv.y = pack2(l2, l3);
    ((uint2*)(ah + base))[tid] = hv;
    ((uint2*)(al + base))[tid] = lv;

    split1(v1.x * inv, h0, l0); split1(v1.y * inv, h1, l1);
    split1(v1.z * inv, h2, l2); split1(v1.w * inv, h3, l3);
    hv.x = pack2(h0, h1); hv.y = pack2(h2, h3);
    lv.x = pack2(l0, l1); lv.y = pack2(l2, l3);
    ((uint2*)(ah + base))[tid + 256] = hv;
    ((uint2*)(al + base))[tid + 256] = lv;
}

// ---------------------------------------------------------------------------
extern "C" void kernel_launch(void* const* d_in, const int* in_sizes, int n_in,
                              void* d_out, int out_size)
{
    const float* x  = (const float*)d_in[0];
    const float* Wq = (const float*)d_in[1];
    const float* bq = (const float*)d_in[2];
    const float* Wk = (const float*)d_in[3];
    const float* bk = (const float*)d_in[4];
    const float* Wv = (const float*)d_in[5];
    const float* bv = (const float*)d_in[6];
    const float* Wm = (const float*)d_in[7];
    const float* bm = (const float*)d_in[8];
    float* out = (float*)d_out;

    __nv_bfloat16 *xh, *xl, *Wqh, *Wql, *Wkh, *Wkl, *Wvh, *Wvl, *Wmh, *Wml;
    __nv_bfloat16 *Qh, *Ql, *Kh, *Kl, *Vth, *Vtl, *Th, *Tl, *ah, *al;
    float *Qf, *Kf, *Vf, *Tf, *S;
    cudaGetSymbolAddress((void**)&xh, g_xh);   cudaGetSymbolAddress((void**)&xl, g_xl);
    cudaGetSymbolAddress((void**)&Wqh, g_Wqh); cudaGetSymbolAddress((void**)&Wql, g_Wql);
    cudaGetSymbolAddress((void**)&Wkh, g_Wkh); cudaGetSymbolAddress((void**)&Wkl, g_Wkl);
    cudaGetSymbolAddress((void**)&Wvh, g_Wvh); cudaGetSymbolAddress((void**)&Wvl, g_Wvl);
    cudaGetSymbolAddress((void**)&Wmh, g_Wmh); cudaGetSymbolAddress((void**)&Wml, g_Wml);
    cudaGetSymbolAddress((void**)&Qf, g_Qf);   cudaGetSymbolAddress((void**)&Kf, g_Kf);
    cudaGetSymbolAddress((void**)&Vf, g_Vf);   cudaGetSymbolAddress((void**)&Tf, g_Tf);
    cudaGetSymbolAddress((void**)&Qh, g_Qh);   cudaGetSymbolAddress((void**)&Ql, g_Ql);
    cudaGetSymbolAddress((void**)&Kh, g_Kh);   cudaGetSymbolAddress((void**)&Kl, g_Kl);
    cudaGetSymbolAddress((void**)&Vth, g_Vth); cudaGetSymbolAddress((void**)&Vtl, g_Vtl);
    cudaGetSymbolAddress((void**)&Th, g_Th);   cudaGetSymbolAddress((void**)&Tl, g_Tl);
    cudaGetSymbolAddress((void**)&ah, g_ah);   cudaGetSymbolAddress((void**)&al, g_al);
    cudaGetSymbolAddress((void**)&S, g_S);

    cudaFuncSetAttribute(gemm_mma<true, false>,
                         cudaFuncAttributeMaxDynamicSharedMemorySize, SMEM_BYTES);
    cudaFuncSetAttribute(gemm_mma<false, false>,
                         cudaFuncAttributeMaxDynamicSharedMemorySize, SMEM_BYTES);
    cudaFuncSetAttribute(gemm_mma<true, true>,
                         cudaFuncAttributeMaxDynamicSharedMemorySize, SMEM_BYTES);

    const long long nX = (long long)BN_TOT * D_EMB;

    // 1) split x
    split_kernel<<<(unsigned)((nX / 4 + 255) / 256), 256>>>(x, xh, xl, nX / 4);

    // 2) transpose-split weights: W[k,n] -> Wt[n,k]
    {
        dim3 g(D_EMB / 32, D_EMB / 32, 1), b(32, 8);
        tsplit_kernel<<<g, b>>>(Wq, Wqh, Wql, D_EMB, D_EMB);
        tsplit_kernel<<<g, b>>>(Wk, Wkh, Wkl, D_EMB, D_EMB);
        tsplit_kernel<<<g, b>>>(Wv, Wvh, Wvl, D_EMB, D_EMB);
        tsplit_kernel<<<g, b>>>(Wm, Wmh, Wml, D_EMB, D_EMB);
    }

    // 3) projections: Q/K/V = x @ W + b  (M=8192, N=1024, K=1024)
    {
        dim3 g(D_EMB / 128, BN_TOT / 128, 1);
        gemm_mma<true, false><<<g, 256, SMEM_BYTES>>>(xh, xl, Wqh, Wql, bq, Qf,
                                                      D_EMB, D_EMB, 0, 0, 0);
        gemm_mma<true, false><<<g, 256, SMEM_BYTES>>>(xh, xl, Wkh, Wkl, bk, Kf,
                                                      D_EMB, D_EMB, 0, 0, 0);
        gemm_mma<true, false><<<g, 256, SMEM_BYTES>>>(xh, xl, Wvh, Wvl, bv, Vf,
                                                      D_EMB, D_EMB, 0, 0, 0);
    }

    // 4) split Q, K
    split_kernel<<<(unsigned)((nX / 4 + 255) / 256), 256>>>(Qf, Qh, Ql, nX / 4);
    split_kernel<<<(unsigned)((nX / 4 + 255) / 256), 256>>>(Kf, Kh, Kl, nX / 4);

    // 5) transpose-split V per batch: [2048,1024] -> [1024,2048]
    {
        dim3 g(D_EMB / 32, N_SEQ / 32, N_BATCH), b(32, 8);
        tsplit_kernel<<<g, b>>>(Vf, Vth, Vtl, N_SEQ, D_EMB);
    }

    // 6) S'[b,j,i] = K_b @ Q_b^T  (M=N=2048, K=1024, batched)
    {
        dim3 g(N_SEQ / 128, N_SEQ / 128, N_BATCH);
        gemm_mma<false, false><<<g, 256, SMEM_BYTES>>>(
            Kh, Kl, Qh, Ql, nullptr, S, N_SEQ, D_EMB,
            (long long)N_SEQ * D_EMB, (long long)N_SEQ * D_EMB,
            (long long)N_SEQ * N_SEQ);
    }

    // 7) row softmax -> alpha hi/lo
    softmax_split<<<BN_TOT, 256>>>(S, ah, al);

    // 8) T[b] = alpha'_b @ V_b  via Vt  (M=2048, N=1024, K=2048, batched)
    {
        dim3 g(D_EMB / 128, N_SEQ / 128, N_BATCH);
        gemm_mma<false, false><<<g, 256, SMEM_BYTES>>>(
            ah, al, Vth, Vtl, nullptr, Tf, D_EMB, N_SEQ,
            (long long)N_SEQ * N_SEQ, (long long)D_EMB * N_SEQ,
            (long long)N_SEQ * D_EMB);
    }

    // 9) split T
    split_kernel<<<(unsigned)((nX / 4 + 255) / 256), 256>>>(Tf, Th, Tl, nX / 4);

    // 10) out = relu(T @ Wm + bm)  (M=8192, N=1024, K=1024)
    {
        dim3 g(D_EMB / 128, BN_TOT / 128, 1);
        gemm_mma<true, true><<<g, 256, SMEM_BYTES>>>(Th, Tl, Wmh, Wml, bm, out,
                                                     D_EMB, D_EMB, 0, 0, 0);
    }
}

// round 5
// speedup vs baseline: 2.4531x; 1.0800x over previous
#include <cuda_runtime.h>
#include <cuda_bf16.h>
#include <stdint.h>
#include <math.h>

#define D_EMB   1024
#define N_BATCH 4
#define N_SEQ   2048
#define BN_TOT  (N_BATCH * N_SEQ)   // 8192

// ---------------------------------------------------------------------------
// Device scratch (allocation-free per harness rules)
// ---------------------------------------------------------------------------
__device__ __nv_bfloat16 g_xh[BN_TOT * D_EMB], g_xl[BN_TOT * D_EMB];
__device__ __nv_bfloat16 g_Wqh[D_EMB * D_EMB], g_Wql[D_EMB * D_EMB];
__device__ __nv_bfloat16 g_Wkh[D_EMB * D_EMB], g_Wkl[D_EMB * D_EMB];
__device__ __nv_bfloat16 g_Wvh[D_EMB * D_EMB], g_Wvl[D_EMB * D_EMB];
__device__ __nv_bfloat16 g_Wmh[D_EMB * D_EMB], g_Wml[D_EMB * D_EMB];
__device__ float g_Vf[BN_TOT * D_EMB];
__device__ __nv_bfloat16 g_Qh[BN_TOT * D_EMB], g_Ql[BN_TOT * D_EMB];
__device__ __nv_bfloat16 g_Kh[BN_TOT * D_EMB], g_Kl[BN_TOT * D_EMB];
__device__ __nv_bfloat16 g_Vth[BN_TOT * D_EMB], g_Vtl[BN_TOT * D_EMB];
__device__ __nv_bfloat16 g_Th[BN_TOT * D_EMB], g_Tl[BN_TOT * D_EMB];
__device__ float g_S[(size_t)N_BATCH * N_SEQ * N_SEQ];
__device__ __nv_bfloat16 g_ah[(size_t)N_BATCH * N_SEQ * N_SEQ];
__device__ __nv_bfloat16 g_al[(size_t)N_BATCH * N_SEQ * N_SEQ];

// ---------------------------------------------------------------------------
// helpers
// ---------------------------------------------------------------------------
__device__ __forceinline__ uint32_t smem_u32(const void* p) {
    uint32_t a;
    asm("{ .reg .u64 t; cvta.to.shared.u64 t, %1; cvt.u32.u64 %0, t; }"
        : "=r"(a) : "l"(p));
    return a;
}
__device__ __forceinline__ uint64_t gptr64(const void* p) {
    uint64_t g;
    asm("cvta.to.global.u64 %0, %1;" : "=l"(g) : "l"(p));
    return g;
}
__device__ __forceinline__ void cp16(uint32_t saddr, const void* g) {
    asm volatile("cp.async.cg.shared.global [%0], [%1], 16;"
                 :: "r"(saddr), "l"(gptr64(g)) : "memory");
}

// warp-level bf16 MMA, fp32 accumulate (fallback HMMA on sm_103)
__device__ __forceinline__ void mma16816(float* c, const uint32_t* a, const uint32_t* b) {
    asm volatile(
        "mma.sync.aligned.m16n8k16.row.col.f32.bf16.bf16.f32 "
        "{%0,%1,%2,%3}, {%4,%5,%6,%7}, {%8,%9}, {%0,%1,%2,%3};"
        : "+f"(c[0]), "+f"(c[1]), "+f"(c[2]), "+f"(c[3])
        : "r"(a[0]), "r"(a[1]), "r"(a[2]), "r"(a[3]), "r"(b[0]), "r"(b[1]));
}
__device__ __forceinline__ void ldm_x4(uint32_t* r, uint32_t addr) {
    asm volatile("ldmatrix.sync.aligned.m8n8.x4.shared.b16 {%0,%1,%2,%3}, [%4];"
                 : "=r"(r[0]), "=r"(r[1]), "=r"(r[2]), "=r"(r[3]) : "r"(addr));
}
// NON-transposed x2: correct for B stored [N,K] row-major (K-contiguous)
__device__ __forceinline__ void ldm_x2(uint32_t* r, uint32_t addr) {
    asm volatile("ldmatrix.sync.aligned.m8n8.x2.shared.b16 {%0,%1}, [%2];"
                 : "=r"(r[0]), "=r"(r[1]) : "r"(addr));
}

__device__ __forceinline__ void split1(float v, __nv_bfloat16& h, __nv_bfloat16& l) {
    h = __float2bfloat16(v);
    l = __float2bfloat16(v - __bfloat162float(h));
}
__device__ __forceinline__ uint32_t pack2(__nv_bfloat16 a, __nv_bfloat16 b) {
    __nv_bfloat162 t; t.x = a; t.y = b;
    return *reinterpret_cast<uint32_t*>(&t);
}

// smem geometry: rows padded to 40 bf16 (80B) -> conflict-free ldmatrix
#define KC          32
#define ROW_PAD     40
#define TILE_ELEMS  (128 * ROW_PAD)              // per matrix tile, bf16 elems
#define TILE_BYTES  (TILE_ELEMS * 2)             // 10240
#define STAGE_BYTES (4 * TILE_BYTES)             // Ah|Al|Bh|Bl = 40960 B
#define N_STAGES    3
#define SMEM_BYTES  (N_STAGES * STAGE_BYTES)     // 122880 B

// ---------------------------------------------------------------------------
// NT GEMM: C = (Ah+Al)[M,K] @ (Bh+Bl)[N,K]^T, 3-product bf16 split.
// CTA 128x128, 8 warps (2x4), warp tile 64x32, 3-stage cp.async pipeline.
// OM=0: fp32 C output; OM=1: bf16 hi/lo split output (Ch, Cl).
// ---------------------------------------------------------------------------
template <int OM, bool BIAS, bool RELU>
__global__ __launch_bounds__(256, 1)
void gemm_mma(const __nv_bfloat16* __restrict__ Ah, const __nv_bfloat16* __restrict__ Al,
              const __nv_bfloat16* __restrict__ Bh, const __nv_bfloat16* __restrict__ Bl,
              const float* __restrict__ bias, float* __restrict__ C,
              __nv_bfloat16* __restrict__ Ch, __nv_bfloat16* __restrict__ Cl,
              int Nn, int Kd, long long sA, long long sB, long long sC)
{
    extern __shared__ __align__(128) char smem[];
    const int tid = threadIdx.x;
    const long long z = blockIdx.z;
    Ah += z * sA; Al += z * sA;
    Bh += z * sB; Bl += z * sB;
    const int row0 = blockIdx.y * 128;
    const int col0 = blockIdx.x * 128;

    const int warp  = tid >> 5;
    const int lane  = tid & 31;
    const int g     = lane >> 2;
    const int t     = lane & 3;
    const int mbase = (warp & 1) * 64;
    const int nbase = (warp >> 1) * 32;

    const uint32_t sbase = smem_u32(smem);

    // per-lane ldmatrix base offsets (within a stage)
    const uint32_t a_off = (uint32_t)(((mbase + (lane & 15)) * ROW_PAD + (lane >> 4) * 8) * 2);
    const uint32_t b_off = (uint32_t)(((nbase + (lane & 7)) * ROW_PAD + ((lane >> 3) & 1) * 8) * 2);

    float acc[4][4][4];
#pragma unroll
    for (int mi = 0; mi < 4; mi++)
#pragma unroll
        for (int ni = 0; ni < 4; ni++)
#pragma unroll
            for (int r = 0; r < 4; r++) acc[mi][ni][r] = 0.f;

    auto load_stage = [&](int st, int kc) {
        const uint32_t sb = sbase + (uint32_t)st * STAGE_BYTES;
        const int k0 = kc * KC;
#pragma unroll
        for (int i = 0; i < 2; i++) {
            const int idx = tid + (i << 8);
            const int r  = idx >> 2;
            const int c4 = idx & 3;
            const uint32_t soff = (uint32_t)(r * 80 + c4 * 16);
            const long long ga = (long long)(row0 + r) * Kd + k0 + c4 * 8;
            const long long gb = (long long)(col0 + r) * Kd + k0 + c4 * 8;
            cp16(sb + soff,                  Ah + ga);
            cp16(sb + 1 * TILE_BYTES + soff, Al + ga);
            cp16(sb + 2 * TILE_BYTES + soff, Bh + gb);
            cp16(sb + 3 * TILE_BYTES + soff, Bl + gb);
        }
        asm volatile("cp.async.commit_group;" ::: "memory");
    };

    auto compute_stage = [&](int st) {
        const uint32_t sb  = sbase + (uint32_t)st * STAGE_BYTES;
        const uint32_t aoh = sb + a_off;
        const uint32_t aol = aoh + TILE_BYTES;
        const uint32_t boh = sb + 2 * TILE_BYTES + b_off;
        const uint32_t bol = boh + TILE_BYTES;
#pragma unroll
        for (int kk = 0; kk < 2; kk++) {
            uint32_t ahf[4][4], alf[4][4], bhf[4][2], blf[4][2];
#pragma unroll
            for (int mi = 0; mi < 4; mi++) ldm_x4(ahf[mi], aoh + mi * 1280 + kk * 32);
#pragma unroll
            for (int mi = 0; mi < 4; mi++) ldm_x4(alf[mi], aol + mi * 1280 + kk * 32);
#pragma unroll
            for (int ni = 0; ni < 4; ni++) ldm_x2(bhf[ni], boh + ni * 640 + kk * 32);
#pragma unroll
            for (int ni = 0; ni < 4; ni++) ldm_x2(blf[ni], bol + ni * 640 + kk * 32);
            // three independent sweeps: acc reuse distance = 16 MMAs
#pragma unroll
            for (int mi = 0; mi < 4; mi++)
#pragma unroll
                for (int ni = 0; ni < 4; ni++) mma16816(acc[mi][ni], ahf[mi], bhf[ni]);
#pragma unroll
            for (int mi = 0; mi < 4; mi++)
#pragma unroll
                for (int ni = 0; ni < 4; ni++) mma16816(acc[mi][ni], ahf[mi], blf[ni]);
#pragma unroll
            for (int mi = 0; mi < 4; mi++)
#pragma unroll
                for (int ni = 0; ni < 4; ni++) mma16816(acc[mi][ni], alf[mi], bhf[ni]);
        }
    };

    const int nc = Kd / KC;
    load_stage(0, 0);
    load_stage(1, 1);

    for (int c = 0; c < nc; c++) {
        if (c + 2 < nc) asm volatile("cp.async.wait_group 1;" ::: "memory");
        else            asm volatile("cp.async.wait_group 0;" ::: "memory");
        __syncthreads();
        compute_stage(c % N_STAGES);
        if (c + 2 < nc) load_stage((c + 2) % N_STAGES, c + 2);
    }

    // ---- epilogue ----
#pragma unroll
    for (int mi = 0; mi < 4; mi++) {
        const long long r = row0 + mbase + mi * 16 + g;
#pragma unroll
        for (int ni = 0; ni < 4; ni++) {
            const int cc = col0 + nbase + ni * 8 + t * 2;
            float2 v0, v1;
            v0.x = acc[mi][ni][0]; v0.y = acc[mi][ni][1];
            v1.x = acc[mi][ni][2]; v1.y = acc[mi][ni][3];
            if (BIAS) {
                const float2 bv = *(const float2*)(bias + cc);
                v0.x += bv.x; v0.y += bv.y;
                v1.x += bv.x; v1.y += bv.y;
            }
            if (RELU) {
                v0.x = fmaxf(v0.x, 0.f); v0.y = fmaxf(v0.y, 0.f);
                v1.x = fmaxf(v1.x, 0.f); v1.y = fmaxf(v1.y, 0.f);
            }
            if (OM == 0) {
                float* Cz = C + z * sC;
                *(float2*)(Cz + r * Nn + cc)       = v0;
                *(float2*)(Cz + (r + 8) * Nn + cc) = v1;
            } else {
                __nv_bfloat16* Chz = Ch + z * sC;
                __nv_bfloat16* Clz = Cl + z * sC;
                __nv_bfloat16 h0, h1, l0, l1;
                split1(v0.x, h0, l0); split1(v0.y, h1, l1);
                *(uint32_t*)(Chz + r * Nn + cc) = pack2(h0, h1);
                *(uint32_t*)(Clz + r * Nn + cc) = pack2(l0, l1);
                split1(v1.x, h0, l0); split1(v1.y, h1, l1);
                *(uint32_t*)(Chz + (r + 8) * Nn + cc) = pack2(h0, h1);
                *(uint32_t*)(Clz + (r + 8) * Nn + cc) = pack2(l0, l1);
            }
        }
    }
}

// ---------------------------------------------------------------------------
// fp32 -> bf16 hi/lo elementwise split (x only)
// ---------------------------------------------------------------------------
__global__ __launch_bounds__(256)
void split_kernel(const float* __restrict__ in, __nv_bfloat16* __restrict__ oh,
                  __nv_bfloat16* __restrict__ ol, long long n4)
{
    long long i = (long long)blockIdx.x * blockDim.x + threadIdx.x;
    if (i >= n4) return;
    float4 v = ((const float4*)in)[i];
    __nv_bfloat16 h0, h1, h2, h3, l0, l1, l2, l3;
    split1(v.x, h0, l0); split1(v.y, h1, l1);
    split1(v.z, h2, l2); split1(v.w, h3, l3);
    uint2 hv, lv;
    hv.x = pack2(h0, h1); hv.y = pack2(h2, h3);
    lv.x = pack2(l0, l1); lv.y = pack2(l2, l3);
    ((uint2*)oh)[i] = hv;
    ((uint2*)ol)[i] = lv;
}

// ---------------------------------------------------------------------------
// fp32 [R,C] -> transposed bf16 hi/lo [C,R] (batched via blockIdx.z)
// ---------------------------------------------------------------------------
__global__ __launch_bounds__(256)
void tsplit_kernel(const float* __restrict__ in, __nv_bfloat16* __restrict__ oh,
                   __nv_bfloat16* __restrict__ ol, int R, int C)
{
    __shared__ float t[32][33];
    const long long zoff = (long long)blockIdx.z * R * C;
    in += zoff; oh += zoff; ol += zoff;
    const int tx = threadIdx.x, ty = threadIdx.y;
    const int x = blockIdx.x * 32 + tx;
    const int y0 = blockIdx.y * 32 + ty;
#pragma unroll
    for (int i = 0; i < 32; i += 8)
        t[ty + i][tx] = in[(long long)(y0 + i) * C + x];
    __syncthreads();
    const int ox = blockIdx.y * 32 + tx;
    const int oy0 = blockIdx.x * 32 + ty;
#pragma unroll
    for (int i = 0; i < 32; i += 8) {
        float v = t[tx][ty + i];
        __nv_bfloat16 h, l;
        split1(v, h, l);
        oh[(long long)(oy0 + i) * R + ox] = h;
        ol[(long long)(oy0 + i) * R + ox] = l;
    }
}

// ---------------------------------------------------------------------------
// Row softmax over 2048 fp32 -> bf16 hi/lo outputs
// ---------------------------------------------------------------------------
__inline__ __device__ float warpMax(float v) {
#pragma unroll
    for (int o = 16; o > 0; o >>= 1) v = fmaxf(v, __shfl_xor_sync(0xffffffffu, v, o));
    return v;
}
__inline__ __device__ float warpSum(float v) {
#pragma unroll
    for (int o = 16; o > 0; o >>= 1) v += __shfl_xor_sync(0xffffffffu, v, o);
    return v;
}

__global__ __launch_bounds__(256)
void softmax_split(const float* __restrict__ S, __nv_bfloat16* __restrict__ ah,
                   __nv_bfloat16* __restrict__ al)
{
    const long long base = (long long)blockIdx.x * N_SEQ;
    const float* row = S + base;
    const int tid = threadIdx.x;
    const int lane = tid & 31;
    const int wid = tid >> 5;

    float4 v0 = ((const float4*)row)[tid];
    float4 v1 = ((const float4*)row)[tid + 256];

    __shared__ float sm[8];
    float m = fmaxf(fmaxf(fmaxf(v0.x, v0.y), fmaxf(v0.z, v0.w)),
                    fmaxf(fmaxf(v1.x, v1.y), fmaxf(v1.z, v1.w)));
    m = warpMax(m);
    if (lane == 0) sm[wid] = m;
    __syncthreads();
    if (wid == 0) {
        float t = (lane < 8) ? sm[lane] : -3.402823e38f;
        t = warpMax(t);
        if (lane == 0) sm[0] = t;
    }
    __syncthreads();
    m = sm[0];
    __syncthreads();

    v0.x = expf(v0.x - m); v0.y = expf(v0.y - m);
    v0.z = expf(v0.z - m); v0.w = expf(v0.w - m);
    v1.x = expf(v1.x - m); v1.y = expf(v1.y - m);
    v1.z = expf(v1.z - m); v1.w = expf(v1.w - m);

    float s = (v0.x + v0.y + v0.z + v0.w) + (v1.x + v1.y + v1.z + v1.w);
    s = warpSum(s);
    if (lane == 0) sm[wid] = s;
    __syncthreads();
    if (wid == 0) {
        float t = (lane < 8) ? sm[lane] : 0.f;
        t = warpSum(t);
        if (lane == 0) sm[0] = t;
    }
    __syncthreads();
    const float inv = 1.0f / sm[0];

    __nv_bfloat16 h0, h1, h2, h3, l0, l1, l2, l3;
    uint2 hv, lv;
    split1(v0.x * inv, h0, l0); split1(v0.y * inv, h1, l1);
    split1(v0.z * inv, h2, l2); split1(v0.w * inv, h3, l3);
    hv.x = pack2(h0, h1); hv.y = pack2(h2, h3);
    lv.x = pack2(l0, l1); lv.y = pack2(l2, l3);
    ((uint2*)(ah + base))[tid] = hv;
    ((uint2*)(al + base))[tid] = lv;

    split1(v1.x * inv, h0, l0); split1(v1.y * inv, h1, l1);
    split1(v1.z * inv, h2, l2); split1(v1.w * inv, h3, l3);
    hv.x = pack2(h0, h1); hv.y = pack2(h2, h3);
    lv.x = pack2(l0, l1); lv.y = pack2(l2, l3);
    ((uint2*)(ah + base))[tid + 256] = hv;
    ((uint2*)(al + base))[tid + 256] = lv;
}

// ---------------------------------------------------------------------------
extern "C" void kernel_launch(void* const* d_in, const int* in_sizes, int n_in,
                              void* d_out, int out_size)
{
    const float* x  = (const float*)d_in[0];
    const float* Wq = (const float*)d_in[1];
    const float* bq = (const float*)d_in[2];
    const float* Wk = (const float*)d_in[3];
    const float* bk = (const float*)d_in[4];
    const float* Wv = (const float*)d_in[5];
    const float* bv = (const float*)d_in[6];
    const float* Wm = (const float*)d_in[7];
    const float* bm = (const float*)d_in[8];
    float* out = (float*)d_out;

    __nv_bfloat16 *xh, *xl, *Wqh, *Wql, *Wkh, *Wkl, *Wvh, *Wvl, *Wmh, *Wml;
    __nv_bfloat16 *Qh, *Ql, *Kh, *Kl, *Vth, *Vtl, *Th, *Tl, *ah, *al;
    float *Vf, *S;
    cudaGetSymbolAddress((void**)&xh, g_xh);   cudaGetSymbolAddress((void**)&xl, g_xl);
    cudaGetSymbolAddress((void**)&Wqh, g_Wqh); cudaGetSymbolAddress((void**)&Wql, g_Wql);
    cudaGetSymbolAddress((void**)&Wkh, g_Wkh); cudaGetSymbolAddress((void**)&Wkl, g_Wkl);
    cudaGetSymbolAddress((void**)&Wvh, g_Wvh); cudaGetSymbolAddress((void**)&Wvl, g_Wvl);
    cudaGetSymbolAddress((void**)&Wmh, g_Wmh); cudaGetSymbolAddress((void**)&Wml, g_Wml);
    cudaGetSymbolAddress((void**)&Vf, g_Vf);
    cudaGetSymbolAddress((void**)&Qh, g_Qh);   cudaGetSymbolAddress((void**)&Ql, g_Ql);
    cudaGetSymbolAddress((void**)&Kh, g_Kh);   cudaGetSymbolAddress((void**)&Kl, g_Kl);
    cudaGetSymbolAddress((void**)&Vth, g_Vth); cudaGetSymbolAddress((void**)&Vtl, g_Vtl);
    cudaGetSymbolAddress((void**)&Th, g_Th);   cudaGetSymbolAddress((void**)&Tl, g_Tl);
    cudaGetSymbolAddress((void**)&ah, g_ah);   cudaGetSymbolAddress((void**)&al, g_al);
    cudaGetSymbolAddress((void**)&S, g_S);

    cudaFuncSetAttribute(gemm_mma<0, true, false>,
                         cudaFuncAttributeMaxDynamicSharedMemorySize, SMEM_BYTES);
    cudaFuncSetAttribute(gemm_mma<0, false, false>,
                         cudaFuncAttributeMaxDynamicSharedMemorySize, SMEM_BYTES);
    cudaFuncSetAttribute(gemm_mma<0, true, true>,
                         cudaFuncAttributeMaxDynamicSharedMemorySize, SMEM_BYTES);
    cudaFuncSetAttribute(gemm_mma<1, true, false>,
                         cudaFuncAttributeMaxDynamicSharedMemorySize, SMEM_BYTES);
    cudaFuncSetAttribute(gemm_mma<1, false, false>,
                         cudaFuncAttributeMaxDynamicSharedMemorySize, SMEM_BYTES);

    const long long nX = (long long)BN_TOT * D_EMB;

    // 1) split x
    split_kernel<<<(unsigned)((nX / 4 + 255) / 256), 256>>>(x, xh, xl, nX / 4);

    // 2) transpose-split weights: W[k,n] -> Wt[n,k]
    {
        dim3 g(D_EMB / 32, D_EMB / 32, 1), b(32, 8);
        tsplit_kernel<<<g, b>>>(Wq, Wqh, Wql, D_EMB, D_EMB);
        tsplit_kernel<<<g, b>>>(Wk, Wkh, Wkl, D_EMB, D_EMB);
        tsplit_kernel<<<g, b>>>(Wv, Wvh, Wvl, D_EMB, D_EMB);
        tsplit_kernel<<<g, b>>>(Wm, Wmh, Wml, D_EMB, D_EMB);
    }

    // 3) projections (Q,K -> split epilogue; V -> fp32 for transpose)
    {
        dim3 g(D_EMB / 128, BN_TOT / 128, 1);
        gemm_mma<1, true, false><<<g, 256, SMEM_BYTES>>>(
            xh, xl, Wqh, Wql, bq, nullptr, Qh, Ql, D_EMB, D_EMB, 0, 0, 0);
        gemm_mma<1, true, false><<<g, 256, SMEM_BYTES>>>(
            xh, xl, Wkh, Wkl, bk, nullptr, Kh, Kl, D_EMB, D_EMB, 0, 0, 0);
        gemm_mma<0, true, false><<<g, 256, SMEM_BYTES>>>(
            xh, xl, Wvh, Wvl, bv, Vf, nullptr, nullptr, D_EMB, D_EMB, 0, 0, 0);
    }

    // 4) transpose-split V per batch: [2048,1024] -> [1024,2048]
    {
        dim3 g(D_EMB / 32, N_SEQ / 32, N_BATCH), b(32, 8);
        tsplit_kernel<<<g, b>>>(Vf, Vth, Vtl, N_SEQ, D_EMB);
    }

    // 5) S'[b,j,i] = K_b @ Q_b^T  (M=N=2048, K=1024, batched)
    {
        dim3 g(N_SEQ / 128, N_SEQ / 128, N_BATCH);
        gemm_mma<0, false, false><<<g, 256, SMEM_BYTES>>>(
            Kh, Kl, Qh, Ql, nullptr, S, nullptr, nullptr, N_SEQ, D_EMB,
            (long long)N_SEQ * D_EMB, (long long)N_SEQ * D_EMB,
            (long long)N_SEQ * N_SEQ);
    }

    // 6) row softmax -> alpha hi/lo
    softmax_split<<<BN_TOT, 256>>>(S, ah, al);

    // 7) T[b] = alpha'_b @ V_b via Vt -> split epilogue (M=2048,N=1024,K=2048)
    {
        dim3 g(D_EMB / 128, N_SEQ / 128, N_BATCH);
        gemm_mma<1, false, false><<<g, 256, SMEM_BYTES>>>(
            ah, al, Vth, Vtl, nullptr, nullptr, Th, Tl, D_EMB, N_SEQ,
            (long long)N_SEQ * N_SEQ, (long long)D_EMB * N_SEQ,
            (long long)N_SEQ * D_EMB);
    }

    // 8) out = relu(T @ Wm + bm)  (M=8192, N=1024, K=1024)
    {
        dim3 g(D_EMB / 128, BN_TOT / 128, 1);
        gemm_mma<0, true, true><<<g, 256, SMEM_BYTES>>>(
            Th, Tl, Wmh, Wml, bm, out, nullptr, nullptr, D_EMB, D_EMB, 0, 0, 0);
    }
}

// round 6
// speedup vs baseline: 2.6888x; 1.0961x over previous
#include <cuda_runtime.h>
#include <cuda_bf16.h>
#include <stdint.h>
#include <math.h>

#define D_EMB   1024
#define N_BATCH 4
#define N_SEQ   2048
#define BN_TOT  (N_BATCH * N_SEQ)   // 8192

// ---------------------------------------------------------------------------
// Device scratch (allocation-free per harness rules)
// ---------------------------------------------------------------------------
__device__ __nv_bfloat16 g_xh[BN_TOT * D_EMB], g_xl[BN_TOT * D_EMB];
__device__ __nv_bfloat16 g_Wqh[D_EMB * D_EMB], g_Wql[D_EMB * D_EMB];  // plain split
__device__ __nv_bfloat16 g_Wkh[D_EMB * D_EMB], g_Wkl[D_EMB * D_EMB];  // plain split
__device__ __nv_bfloat16 g_Wvh[D_EMB * D_EMB], g_Wvl[D_EMB * D_EMB];  // transposed split
__device__ __nv_bfloat16 g_Wmh[D_EMB * D_EMB], g_Wml[D_EMB * D_EMB];  // transposed split
__device__ __nv_bfloat16 g_M2h[D_EMB * D_EMB], g_M2l[D_EMB * D_EMB];  // Wq*Wk^T
__device__ __nv_bfloat16 g_Zh[BN_TOT * D_EMB], g_Zl[BN_TOT * D_EMB];  // x*M
__device__ float g_Vf[BN_TOT * D_EMB];
__device__ __nv_bfloat16 g_Vth[BN_TOT * D_EMB], g_Vtl[BN_TOT * D_EMB];
__device__ __nv_bfloat16 g_Th[BN_TOT * D_EMB], g_Tl[BN_TOT * D_EMB];
__device__ float g_S[(size_t)N_BATCH * N_SEQ * N_SEQ];
__device__ __nv_bfloat16 g_ah[(size_t)N_BATCH * N_SEQ * N_SEQ];
__device__ __nv_bfloat16 g_al[(size_t)N_BATCH * N_SEQ * N_SEQ];
__device__ float g_wv[D_EMB];     // Wq * bk
__device__ float g_w[BN_TOT];     // x * (Wq*bk)  -- per-query softmax offset

// ---------------------------------------------------------------------------
// helpers
// ---------------------------------------------------------------------------
__device__ __forceinline__ uint32_t smem_u32(const void* p) {
    uint32_t a;
    asm("{ .reg .u64 t; cvta.to.shared.u64 t, %1; cvt.u32.u64 %0, t; }"
        : "=r"(a) : "l"(p));
    return a;
}
__device__ __forceinline__ uint64_t gptr64(const void* p) {
    uint64_t g;
    asm("cvta.to.global.u64 %0, %1;" : "=l"(g) : "l"(p));
    return g;
}
__device__ __forceinline__ void cp16(uint32_t saddr, const void* g) {
    asm volatile("cp.async.cg.shared.global [%0], [%1], 16;"
                 :: "r"(saddr), "l"(gptr64(g)) : "memory");
}

// warp-level bf16 MMA, fp32 accumulate (fallback HMMA on sm_103)
__device__ __forceinline__ void mma16816(float* c, const uint32_t* a, const uint32_t* b) {
    asm volatile(
        "mma.sync.aligned.m16n8k16.row.col.f32.bf16.bf16.f32 "
        "{%0,%1,%2,%3}, {%4,%5,%6,%7}, {%8,%9}, {%0,%1,%2,%3};"
        : "+f"(c[0]), "+f"(c[1]), "+f"(c[2]), "+f"(c[3])
        : "r"(a[0]), "r"(a[1]), "r"(a[2]), "r"(a[3]), "r"(b[0]), "r"(b[1]));
}
__device__ __forceinline__ void ldm_x4(uint32_t* r, uint32_t addr) {
    asm volatile("ldmatrix.sync.aligned.m8n8.x4.shared.b16 {%0,%1,%2,%3}, [%4];"
                 : "=r"(r[0]), "=r"(r[1]), "=r"(r[2]), "=r"(r[3]) : "r"(addr));
}
// NON-transposed x2: correct for B stored [N,K] row-major (K-contiguous)
__device__ __forceinline__ void ldm_x2(uint32_t* r, uint32_t addr) {
    asm volatile("ldmatrix.sync.aligned.m8n8.x2.shared.b16 {%0,%1}, [%2];"
                 : "=r"(r[0]), "=r"(r[1]) : "r"(addr));
}

__device__ __forceinline__ void split1(float v, __nv_bfloat16& h, __nv_bfloat16& l) {
    h = __float2bfloat16(v);
    l = __float2bfloat16(v - __bfloat162float(h));
}
__device__ __forceinline__ uint32_t pack2(__nv_bfloat16 a, __nv_bfloat16 b) {
    __nv_bfloat162 t; t.x = a; t.y = b;
    return *reinterpret_cast<uint32_t*>(&t);
}

// smem geometry: rows padded to 40 bf16 (80B) -> conflict-free ldmatrix
#define KC          32
#define ROW_PAD     40
#define TILE_ELEMS  (128 * ROW_PAD)
#define TILE_BYTES  (TILE_ELEMS * 2)             // 10240
#define STAGE_BYTES (4 * TILE_BYTES)             // 40960
#define N_STAGES    3
#define SMEM_BYTES  (N_STAGES * STAGE_BYTES)     // 122880

// ---------------------------------------------------------------------------
// NT GEMM: C = (Ah+Al)[M,K] @ (Bh+Bl)[N,K]^T, 3-product bf16 split.
// CTA 128x128, 8 warps (2x4), warp tile 64x32, 3-stage cp.async pipeline.
// OM=0: fp32 C output; OM=1: bf16 hi/lo split output (Ch, Cl).
// ---------------------------------------------------------------------------
template <int OM, bool BIAS, bool RELU>
__global__ __launch_bounds__(256, 1)
void gemm_mma(const __nv_bfloat16* __restrict__ Ah, const __nv_bfloat16* __restrict__ Al,
              const __nv_bfloat16* __restrict__ Bh, const __nv_bfloat16* __restrict__ Bl,
              const float* __restrict__ bias, float* __restrict__ C,
              __nv_bfloat16* __restrict__ Ch, __nv_bfloat16* __restrict__ Cl,
              int Nn, int Kd, long long sA, long long sB, long long sC)
{
    extern __shared__ __align__(128) char smem[];
    const int tid = threadIdx.x;
    const long long z = blockIdx.z;
    Ah += z * sA; Al += z * sA;
    Bh += z * sB; Bl += z * sB;
    const int row0 = blockIdx.y * 128;
    const int col0 = blockIdx.x * 128;

    const int warp  = tid >> 5;
    const int lane  = tid & 31;
    const int g     = lane >> 2;
    const int t     = lane & 3;
    const int mbase = (warp & 1) * 64;
    const int nbase = (warp >> 1) * 32;

    const uint32_t sbase = smem_u32(smem);

    const uint32_t a_off = (uint32_t)(((mbase + (lane & 15)) * ROW_PAD + (lane >> 4) * 8) * 2);
    const uint32_t b_off = (uint32_t)(((nbase + (lane & 7)) * ROW_PAD + ((lane >> 3) & 1) * 8) * 2);

    float acc[4][4][4];
#pragma unroll
    for (int mi = 0; mi < 4; mi++)
#pragma unroll
        for (int ni = 0; ni < 4; ni++)
#pragma unroll
            for (int r = 0; r < 4; r++) acc[mi][ni][r] = 0.f;

    auto load_stage = [&](int st, int kc) {
        const uint32_t sb = sbase + (uint32_t)st * STAGE_BYTES;
        const int k0 = kc * KC;
#pragma unroll
        for (int i = 0; i < 2; i++) {
            const int idx = tid + (i << 8);
            const int r  = idx >> 2;
            const int c4 = idx & 3;
            const uint32_t soff = (uint32_t)(r * 80 + c4 * 16);
            const long long ga = (long long)(row0 + r) * Kd + k0 + c4 * 8;
            const long long gb = (long long)(col0 + r) * Kd + k0 + c4 * 8;
            cp16(sb + soff,                  Ah + ga);
            cp16(sb + 1 * TILE_BYTES + soff, Al + ga);
            cp16(sb + 2 * TILE_BYTES + soff, Bh + gb);
            cp16(sb + 3 * TILE_BYTES + soff, Bl + gb);
        }
        asm volatile("cp.async.commit_group;" ::: "memory");
    };

    auto compute_stage = [&](int st) {
        const uint32_t sb  = sbase + (uint32_t)st * STAGE_BYTES;
        const uint32_t aoh = sb + a_off;
        const uint32_t aol = aoh + TILE_BYTES;
        const uint32_t boh = sb + 2 * TILE_BYTES + b_off;
        const uint32_t bol = boh + TILE_BYTES;
#pragma unroll
        for (int kk = 0; kk < 2; kk++) {
            uint32_t ahf[4][4], alf[4][4], bhf[4][2], blf[4][2];
#pragma unroll
            for (int mi = 0; mi < 4; mi++) ldm_x4(ahf[mi], aoh + mi * 1280 + kk * 32);
#pragma unroll
            for (int mi = 0; mi < 4; mi++) ldm_x4(alf[mi], aol + mi * 1280 + kk * 32);
#pragma unroll
            for (int ni = 0; ni < 4; ni++) ldm_x2(bhf[ni], boh + ni * 640 + kk * 32);
#pragma unroll
            for (int ni = 0; ni < 4; ni++) ldm_x2(blf[ni], bol + ni * 640 + kk * 32);
#pragma unroll
            for (int mi = 0; mi < 4; mi++)
#pragma unroll
                for (int ni = 0; ni < 4; ni++) mma16816(acc[mi][ni], ahf[mi], bhf[ni]);
#pragma unroll
            for (int mi = 0; mi < 4; mi++)
#pragma unroll
                for (int ni = 0; ni < 4; ni++) mma16816(acc[mi][ni], ahf[mi], blf[ni]);
#pragma unroll
            for (int mi = 0; mi < 4; mi++)
#pragma unroll
                for (int ni = 0; ni < 4; ni++) mma16816(acc[mi][ni], alf[mi], bhf[ni]);
        }
    };

    const int nc = Kd / KC;
    load_stage(0, 0);
    load_stage(1, 1);

    for (int c = 0; c < nc; c++) {
        if (c + 2 < nc) asm volatile("cp.async.wait_group 1;" ::: "memory");
        else            asm volatile("cp.async.wait_group 0;" ::: "memory");
        __syncthreads();
        compute_stage(c % N_STAGES);
        if (c + 2 < nc) load_stage((c + 2) % N_STAGES, c + 2);
    }

    // ---- epilogue ----
#pragma unroll
    for (int mi = 0; mi < 4; mi++) {
        const long long r = row0 + mbase + mi * 16 + g;
#pragma unroll
        for (int ni = 0; ni < 4; ni++) {
            const int cc = col0 + nbase + ni * 8 + t * 2;
            float2 v0, v1;
            v0.x = acc[mi][ni][0]; v0.y = acc[mi][ni][1];
            v1.x = acc[mi][ni][2]; v1.y = acc[mi][ni][3];
            if (BIAS) {
                const float2 bv = *(const float2*)(bias + cc);
                v0.x += bv.x; v0.y += bv.y;
                v1.x += bv.x; v1.y += bv.y;
            }
            if (RELU) {
                v0.x = fmaxf(v0.x, 0.f); v0.y = fmaxf(v0.y, 0.f);
                v1.x = fmaxf(v1.x, 0.f); v1.y = fmaxf(v1.y, 0.f);
            }
            if (OM == 0) {
                float* Cz = C + z * sC;
                *(float2*)(Cz + r * Nn + cc)       = v0;
                *(float2*)(Cz + (r + 8) * Nn + cc) = v1;
            } else {
                __nv_bfloat16* Chz = Ch + z * sC;
                __nv_bfloat16* Clz = Cl + z * sC;
                __nv_bfloat16 h0, h1, l0, l1;
                split1(v0.x, h0, l0); split1(v0.y, h1, l1);
                *(uint32_t*)(Chz + r * Nn + cc) = pack2(h0, h1);
                *(uint32_t*)(Clz + r * Nn + cc) = pack2(l0, l1);
                split1(v1.x, h0, l0); split1(v1.y, h1, l1);
                *(uint32_t*)(Chz + (r + 8) * Nn + cc) = pack2(h0, h1);
                *(uint32_t*)(Clz + (r + 8) * Nn + cc) = pack2(l0, l1);
            }
        }
    }
}

// ---------------------------------------------------------------------------
// fp32 -> bf16 hi/lo elementwise split
// ---------------------------------------------------------------------------
__global__ __launch_bounds__(256)
void split_kernel(const float* __restrict__ in, __nv_bfloat16* __restrict__ oh,
                  __nv_bfloat16* __restrict__ ol, long long n4)
{
    long long i = (long long)blockIdx.x * blockDim.x + threadIdx.x;
    if (i >= n4) return;
    float4 v = ((const float4*)in)[i];
    __nv_bfloat16 h0, h1, h2, h3, l0, l1, l2, l3;
    split1(v.x, h0, l0); split1(v.y, h1, l1);
    split1(v.z, h2, l2); split1(v.w, h3, l3);
    uint2 hv, lv;
    hv.x = pack2(h0, h1); hv.y = pack2(h2, h3);
    lv.x = pack2(l0, l1); lv.y = pack2(l2, l3);
    ((uint2*)oh)[i] = hv;
    ((uint2*)ol)[i] = lv;
}

// ---------------------------------------------------------------------------
// fp32 [R,C] -> transposed bf16 hi/lo [C,R] (batched via blockIdx.z)
// ---------------------------------------------------------------------------
__global__ __launch_bounds__(256)
void tsplit_kernel(const float* __restrict__ in, __nv_bfloat16* __restrict__ oh,
                   __nv_bfloat16* __restrict__ ol, int R, int C)
{
    __shared__ float t[32][33];
    const long long zoff = (long long)blockIdx.z * R * C;
    in += zoff; oh += zoff; ol += zoff;
    const int tx = threadIdx.x, ty = threadIdx.y;
    const int x = blockIdx.x * 32 + tx;
    const int y0 = blockIdx.y * 32 + ty;
#pragma unroll
    for (int i = 0; i < 32; i += 8)
        t[ty + i][tx] = in[(long long)(y0 + i) * C + x];
    __syncthreads();
    const int ox = blockIdx.y * 32 + tx;
    const int oy0 = blockIdx.x * 32 + ty;
#pragma unroll
    for (int i = 0; i < 32; i += 8) {
        float v = t[tx][ty + i];
        __nv_bfloat16 h, l;
        split1(v, h, l);
        oh[(long long)(oy0 + i) * R + ox] = h;
        ol[(long long)(oy0 + i) * R + ox] = l;
    }
}

// ---------------------------------------------------------------------------
// warp-per-row matvec: out[r] = sum_c Mrow[r,:]*v[:]   (C = D_EMB)
// ---------------------------------------------------------------------------
__inline__ __device__ float warpSum(float v) {
#pragma unroll
    for (int o = 16; o > 0; o >>= 1) v += __shfl_xor_sync(0xffffffffu, v, o);
    return v;
}
__inline__ __device__ float warpMax(float v) {
#pragma unroll
    for (int o = 16; o > 0; o >>= 1) v = fmaxf(v, __shfl_xor_sync(0xffffffffu, v, o));
    return v;
}

__global__ __launch_bounds__(256)
void matvec_kernel(const float* __restrict__ Mrow, const float* __restrict__ v,
                   float* __restrict__ out)
{
    const int row  = blockIdx.x * 8 + (threadIdx.x >> 5);
    const int lane = threadIdx.x & 31;
    const float* R = Mrow + (long long)row * D_EMB;
    float s = 0.f;
#pragma unroll
    for (int d = lane * 4; d < D_EMB; d += 128) {
        const float4 a = *(const float4*)(R + d);
        const float4 b = *(const float4*)(v + d);
        s += a.x * b.x + a.y * b.y + a.z * b.z + a.w * b.w;
    }
    s = warpSum(s);
    if (lane == 0) out[row] = s;
}

// ---------------------------------------------------------------------------
// Row softmax over 2048 fp32 (+ per-i offset w) -> bf16 hi/lo outputs
// ---------------------------------------------------------------------------
__global__ __launch_bounds__(256)
void softmax_split(const float* __restrict__ S, const float* __restrict__ w,
                   __nv_bfloat16* __restrict__ ah, __nv_bfloat16* __restrict__ al)
{
    const long long base = (long long)blockIdx.x * N_SEQ;
    const float* row = S + base;
    const float* wb  = w + (long long)(blockIdx.x >> 11) * N_SEQ;  // batch = blk / 2048
    const int tid = threadIdx.x;
    const int lane = tid & 31;
    const int wid = tid >> 5;

    float4 v0 = ((const float4*)row)[tid];
    float4 v1 = ((const float4*)row)[tid + 256];
    const float4 w0 = ((const float4*)wb)[tid];
    const float4 w1 = ((const float4*)wb)[tid + 256];
    v0.x += w0.x; v0.y += w0.y; v0.z += w0.z; v0.w += w0.w;
    v1.x += w1.x; v1.y += w1.y; v1.z += w1.z; v1.w += w1.w;

    __shared__ float sm[8];
    float m = fmaxf(fmaxf(fmaxf(v0.x, v0.y), fmaxf(v0.z, v0.w)),
                    fmaxf(fmaxf(v1.x, v1.y), fmaxf(v1.z, v1.w)));
    m = warpMax(m);
    if (lane == 0) sm[wid] = m;
    __syncthreads();
    if (wid == 0) {
        float t = (lane < 8) ? sm[lane] : -3.402823e38f;
        t = warpMax(t);
        if (lane == 0) sm[0] = t;
    }
    __syncthreads();
    m = sm[0];
    __syncthreads();

    v0.x = expf(v0.x - m); v0.y = expf(v0.y - m);
    v0.z = expf(v0.z - m); v0.w = expf(v0.w - m);
    v1.x = expf(v1.x - m); v1.y = expf(v1.y - m);
    v1.z = expf(v1.z - m); v1.w = expf(v1.w - m);

    float s = (v0.x + v0.y + v0.z + v0.w) + (v1.x + v1.y + v1.z + v1.w);
    s = warpSum(s);
    if (lane == 0) sm[wid] = s;
    __syncthreads();
    if (wid == 0) {
        float t = (lane < 8) ? sm[lane] : 0.f;
        t = warpSum(t);
        if (lane == 0) sm[0] = t;
    }
    __syncthreads();
    const float inv = 1.0f / sm[0];

    __nv_bfloat16 h0, h1, h2, h3, l0, l1, l2, l3;
    uint2 hv, lv;
    split1(v0.x * inv, h0, l0); split1(v0.y * inv, h1, l1);
    split1(v0.z * inv, h2, l2); split1(v0.w * inv, h3, l3);
    hv.x = pack2(h0, h1); hv.y = pack2(h2, h3);
    lv.x = pack2(l0, l1); lv.y = pack2(l2, l3);
    ((uint2*)(ah + base))[tid] = hv;
    ((uint2*)(al + base))[tid] = lv;

    split1(v1.x * inv, h0, l0); split1(v1.y * inv, h1, l1);
    split1(v1.z * inv, h2, l2); split1(v1.w * inv, h3, l3);
    hv.x = pack2(h0, h1); hv.y = pack2(h2, h3);
    lv.x = pack2(l0, l1); lv.y = pack2(l2, l3);
    ((uint2*)(ah + base))[tid + 256] = hv;
    ((uint2*)(al + base))[tid + 256] = lv;
}

// ---------------------------------------------------------------------------
extern "C" void kernel_launch(void* const* d_in, const int* in_sizes, int n_in,
                              void* d_out, int out_size)
{
    const float* x  = (const float*)d_in[0];
    const float* Wq = (const float*)d_in[1];
    const float* bq = (const float*)d_in[2];
    const float* Wk = (const float*)d_in[3];
    const float* bk = (const float*)d_in[4];
    const float* Wv = (const float*)d_in[5];
    const float* bv = (const float*)d_in[6];
    const float* Wm = (const float*)d_in[7];
    const float* bm = (const float*)d_in[8];
    float* out = (float*)d_out;
    (void)bq;  // bq enters scores only via terms constant along the softmax axis

    __nv_bfloat16 *xh, *xl, *Wqh, *Wql, *Wkh, *Wkl, *Wvh, *Wvl, *Wmh, *Wml;
    __nv_bfloat16 *M2h, *M2l, *Zh, *Zl, *Vth, *Vtl, *Th, *Tl, *ah, *al;
    float *Vf, *S, *wv, *w;
    cudaGetSymbolAddress((void**)&xh, g_xh);   cudaGetSymbolAddress((void**)&xl, g_xl);
    cudaGetSymbolAddress((void**)&Wqh, g_Wqh); cudaGetSymbolAddress((void**)&Wql, g_Wql);
    cudaGetSymbolAddress((void**)&Wkh, g_Wkh); cudaGetSymbolAddress((void**)&Wkl, g_Wkl);
    cudaGetSymbolAddress((void**)&Wvh, g_Wvh); cudaGetSymbolAddress((void**)&Wvl, g_Wvl);
    cudaGetSymbolAddress((void**)&Wmh, g_Wmh); cudaGetSymbolAddress((void**)&Wml, g_Wml);
    cudaGetSymbolAddress((void**)&M2h, g_M2h); cudaGetSymbolAddress((void**)&M2l, g_M2l);
    cudaGetSymbolAddress((void**)&Zh, g_Zh);   cudaGetSymbolAddress((void**)&Zl, g_Zl);
    cudaGetSymbolAddress((void**)&Vf, g_Vf);
    cudaGetSymbolAddress((void**)&Vth, g_Vth); cudaGetSymbolAddress((void**)&Vtl, g_Vtl);
    cudaGetSymbolAddress((void**)&Th, g_Th);   cudaGetSymbolAddress((void**)&Tl, g_Tl);
    cudaGetSymbolAddress((void**)&ah, g_ah);   cudaGetSymbolAddress((void**)&al, g_al);
    cudaGetSymbolAddress((void**)&S, g_S);
    cudaGetSymbolAddress((void**)&wv, g_wv);   cudaGetSymbolAddress((void**)&w, g_w);

    cudaFuncSetAttribute(gemm_mma<0, true, false>,
                         cudaFuncAttributeMaxDynamicSharedMemorySize, SMEM_BYTES);
    cudaFuncSetAttribute(gemm_mma<0, false, false>,
                         cudaFuncAttributeMaxDynamicSharedMemorySize, SMEM_BYTES);
    cudaFuncSetAttribute(gemm_mma<0, true, true>,
                         cudaFuncAttributeMaxDynamicSharedMemorySize, SMEM_BYTES);
    cudaFuncSetAttribute(gemm_mma<1, true, false>,
                         cudaFuncAttributeMaxDynamicSharedMemorySize, SMEM_BYTES);
    cudaFuncSetAttribute(gemm_mma<1, false, false>,
                         cudaFuncAttributeMaxDynamicSharedMemorySize, SMEM_BYTES);

    const long long nX = (long long)BN_TOT * D_EMB;
    const long long nW = (long long)D_EMB * D_EMB;

    // 1) split x (plain); split Wq, Wk (plain, K-contiguous rows)
    split_kernel<<<(unsigned)((nX / 4 + 255) / 256), 256>>>(x, xh, xl, nX / 4);
    split_kernel<<<(unsigned)((nW / 4 + 255) / 256), 256>>>(Wq, Wqh, Wql, nW / 4);
    split_kernel<<<(unsigned)((nW / 4 + 255) / 256), 256>>>(Wk, Wkh, Wkl, nW / 4);

    // 2) transpose-split Wv, Wm (used as [n,k] B operands)
    {
        dim3 g(D_EMB / 32, D_EMB / 32, 1), b(32, 8);
        tsplit_kernel<<<g, b>>>(Wv, Wvh, Wvl, D_EMB, D_EMB);
        tsplit_kernel<<<g, b>>>(Wm, Wmh, Wml, D_EMB, D_EMB);
    }

    // 3) M2[f,e] = sum_d Wq[f,d]*Wk[e,d]  (= (Wk Wq^T)^T), split epilogue
    {
        dim3 g(D_EMB / 128, D_EMB / 128, 1);
        gemm_mma<1, false, false><<<g, 256, SMEM_BYTES>>>(
            Wqh, Wql, Wkh, Wkl, nullptr, nullptr, M2h, M2l, D_EMB, D_EMB, 0, 0, 0);
    }

    // 4) bias correction vector: wv = Wq*bk ; w = x*wv  (exact rank-1 term)
    matvec_kernel<<<D_EMB / 8, 256>>>(Wq, bk, wv);
    matvec_kernel<<<BN_TOT / 8, 256>>>(x, wv, w);

    // 5) V projection: V = x @ Wv + bv (fp32), then transpose-split per batch
    {
        dim3 g(D_EMB / 128, BN_TOT / 128, 1);
        gemm_mma<0, true, false><<<g, 256, SMEM_BYTES>>>(
            xh, xl, Wvh, Wvl, bv, Vf, nullptr, nullptr, D_EMB, D_EMB, 0, 0, 0);
        dim3 gt(D_EMB / 32, N_SEQ / 32, N_BATCH), bt(32, 8);
        tsplit_kernel<<<gt, bt>>>(Vf, Vth, Vtl, N_SEQ, D_EMB);
    }

    // 6) Z = x @ M  (Z[r,f] = sum_e x[r,e] M2[f,e]), split epilogue
    {
        dim3 g(D_EMB / 128, BN_TOT / 128, 1);
        gemm_mma<1, false, false><<<g, 256, SMEM_BYTES>>>(
            xh, xl, M2h, M2l, nullptr, nullptr, Zh, Zl, D_EMB, D_EMB, 0, 0, 0);
    }

    // 7) S'[b,j,i] = Z_b[j,:] . x_b[i,:]  (M=N=2048, K=1024, batched)
    {
        dim3 g(N_SEQ / 128, N_SEQ / 128, N_BATCH);
        gemm_mma<0, false, false><<<g, 256, SMEM_BYTES>>>(
            Zh, Zl, xh, xl, nullptr, S, nullptr, nullptr, N_SEQ, D_EMB,
            (long long)N_SEQ * D_EMB, (long long)N_SEQ * D_EMB,
            (long long)N_SEQ * N_SEQ);
    }

    // 8) row softmax (with +w_i offset) -> alpha hi/lo
    softmax_split<<<BN_TOT, 256>>>(S, w, ah, al);

    // 9) T[b] = alpha'_b @ V_b via Vt -> split epilogue (M=2048,N=1024,K=2048)
    {
        dim3 g(D_EMB / 128, N_SEQ / 128, N_BATCH);
        gemm_mma<1, false, false><<<g, 256, SMEM_BYTES>>>(
            ah, al, Vth, Vtl, nullptr, nullptr, Th, Tl, D_EMB, N_SEQ,
            (long long)N_SEQ * N_SEQ, (long long)D_EMB * N_SEQ,
            (long long)N_SEQ * D_EMB);
    }

    // 10) out = relu(T @ Wm + bm)  (M=8192, N=1024, K=1024)
    {
        dim3 g(D_EMB / 128, BN_TOT / 128, 1);
        gemm_mma<0, true, true><<<g, 256, SMEM_BYTES>>>(
            Th, Tl, Wmh, Wml, bm, out, nullptr, nullptr, D_EMB, D_EMB, 0, 0, 0);
    }
}

// round 7
// speedup vs baseline: 3.1561x; 1.1738x over previous
#include <cuda_runtime.h>
#include <cuda_fp16.h>
#include <stdint.h>
#include <math.h>

#define D_EMB   1024
#define N_BATCH 4
#define N_SEQ   2048
#define BN_TOT  (N_BATCH * N_SEQ)   // 8192

// ---------------------------------------------------------------------------
// Device scratch (allocation-free per harness rules)
// ---------------------------------------------------------------------------
__device__ __half g_xh[BN_TOT * D_EMB], g_xl[BN_TOT * D_EMB];
__device__ __half g_Wqh[D_EMB * D_EMB], g_Wql[D_EMB * D_EMB];  // plain split
__device__ __half g_Wkh[D_EMB * D_EMB], g_Wkl[D_EMB * D_EMB];  // plain split
__device__ __half g_Wvh[D_EMB * D_EMB], g_Wvl[D_EMB * D_EMB];  // transposed split
__device__ __half g_Wmh[D_EMB * D_EMB], g_Wml[D_EMB * D_EMB];  // transposed split
__device__ __half g_M2h[D_EMB * D_EMB], g_M2l[D_EMB * D_EMB];  // Wq*Wk^T
__device__ __half g_Zh[BN_TOT * D_EMB], g_Zl[BN_TOT * D_EMB];  // x*M
__device__ float g_Vf[BN_TOT * D_EMB];
__device__ __half g_Vth[BN_TOT * D_EMB], g_Vtl[BN_TOT * D_EMB];
__device__ __half g_Th[BN_TOT * D_EMB], g_Tl[BN_TOT * D_EMB];
__device__ float g_S[(size_t)N_BATCH * N_SEQ * N_SEQ];
__device__ __half g_ah[(size_t)N_BATCH * N_SEQ * N_SEQ];
__device__ __half g_al[(size_t)N_BATCH * N_SEQ * N_SEQ];
__device__ float g_wv[D_EMB];     // Wq * bk
__device__ float g_w[BN_TOT];     // x * (Wq*bk)  -- per-query softmax offset

// ---------------------------------------------------------------------------
// helpers
// ---------------------------------------------------------------------------
__device__ __forceinline__ uint32_t smem_u32(const void* p) {
    uint32_t a;
    asm("{ .reg .u64 t; cvta.to.shared.u64 t, %1; cvt.u32.u64 %0, t; }"
        : "=r"(a) : "l"(p));
    return a;
}
__device__ __forceinline__ uint64_t gptr64(const void* p) {
    uint64_t g;
    asm("cvta.to.global.u64 %0, %1;" : "=l"(g) : "l"(p));
    return g;
}
__device__ __forceinline__ void cp16(uint32_t saddr, const void* g) {
    asm volatile("cp.async.cg.shared.global [%0], [%1], 16;"
                 :: "r"(saddr), "l"(gptr64(g)) : "memory");
}

// warp-level fp16 MMA, fp32 accumulate (fallback HMMA on sm_103)
__device__ __forceinline__ void mma16816(float* c, const uint32_t* a, const uint32_t* b) {
    asm volatile(
        "mma.sync.aligned.m16n8k16.row.col.f32.f16.f16.f32 "
        "{%0,%1,%2,%3}, {%4,%5,%6,%7}, {%8,%9}, {%0,%1,%2,%3};"
        : "+f"(c[0]), "+f"(c[1]), "+f"(c[2]), "+f"(c[3])
        : "r"(a[0]), "r"(a[1]), "r"(a[2]), "r"(a[3]), "r"(b[0]), "r"(b[1]));
}
__device__ __forceinline__ void ldm_x4(uint32_t* r, uint32_t addr) {
    asm volatile("ldmatrix.sync.aligned.m8n8.x4.shared.b16 {%0,%1,%2,%3}, [%4];"
                 : "=r"(r[0]), "=r"(r[1]), "=r"(r[2]), "=r"(r[3]) : "r"(addr));
}
// NON-transposed x2: correct for B stored [N,K] row-major (K-contiguous)
__device__ __forceinline__ void ldm_x2(uint32_t* r, uint32_t addr) {
    asm volatile("ldmatrix.sync.aligned.m8n8.x2.shared.b16 {%0,%1}, [%2];"
                 : "=r"(r[0]), "=r"(r[1]) : "r"(addr));
}

__device__ __forceinline__ void split1(float v, __half& h, __half& l) {
    h = __float2half(v);
    l = __float2half(v - __half2float(h));
}
__device__ __forceinline__ uint32_t pack2(__half a, __half b) {
    __half2 t; t.x = a; t.y = b;
    return *reinterpret_cast<uint32_t*>(&t);
}

// smem geometry: rows padded to 40 fp16 (80B) -> conflict-free ldmatrix
#define KC          32
#define ROW_PAD     40
#define TILE_ELEMS  (128 * ROW_PAD)
#define TILE_BYTES  (TILE_ELEMS * 2)             // 10240
#define STAGE_BYTES (4 * TILE_BYTES)             // 40960
#define N_STAGES    3
#define SMEM_BYTES  (N_STAGES * STAGE_BYTES)     // 122880

// ---------------------------------------------------------------------------
// NT GEMM: C = (Ah+Al)[M,K] @ (Bh+Bl)[N,K]^T, fp16 split.
// NPROD=3: hh + hl + lh (near-fp32). NPROD=2: hh + lh (B_lo never loaded).
// CTA 128x128, 8 warps (2x4), warp tile 64x32, 3-stage cp.async pipeline.
// OM=0: fp32 C output; OM=1: fp16 hi/lo split output (Ch, Cl).
// ---------------------------------------------------------------------------
template <int NPROD, int OM, bool BIAS, bool RELU>
__global__ __launch_bounds__(256, 1)
void gemm_mma(const __half* __restrict__ Ah, const __half* __restrict__ Al,
              const __half* __restrict__ Bh, const __half* __restrict__ Bl,
              const float* __restrict__ bias, float* __restrict__ C,
              __half* __restrict__ Ch, __half* __restrict__ Cl,
              int Nn, int Kd, long long sA, long long sB, long long sC)
{
    extern __shared__ __align__(128) char smem[];
    const int tid = threadIdx.x;
    const long long z = blockIdx.z;
    Ah += z * sA; Al += z * sA;
    Bh += z * sB;
    if (NPROD == 3) Bl += z * sB;
    const int row0 = blockIdx.y * 128;
    const int col0 = blockIdx.x * 128;

    const int warp  = tid >> 5;
    const int lane  = tid & 31;
    const int g     = lane >> 2;
    const int t     = lane & 3;
    const int mbase = (warp & 1) * 64;
    const int nbase = (warp >> 1) * 32;

    const uint32_t sbase = smem_u32(smem);

    const uint32_t a_off = (uint32_t)(((mbase + (lane & 15)) * ROW_PAD + (lane >> 4) * 8) * 2);
    const uint32_t b_off = (uint32_t)(((nbase + (lane & 7)) * ROW_PAD + ((lane >> 3) & 1) * 8) * 2);

    float acc[4][4][4];
#pragma unroll
    for (int mi = 0; mi < 4; mi++)
#pragma unroll
        for (int ni = 0; ni < 4; ni++)
#pragma unroll
            for (int r = 0; r < 4; r++) acc[mi][ni][r] = 0.f;

    auto load_stage = [&](int st, int kc) {
        const uint32_t sb = sbase + (uint32_t)st * STAGE_BYTES;
        const int k0 = kc * KC;
#pragma unroll
        for (int i = 0; i < 2; i++) {
            const int idx = tid + (i << 8);
            const int r  = idx >> 2;
            const int c4 = idx & 3;
            const uint32_t soff = (uint32_t)(r * 80 + c4 * 16);
            const long long ga = (long long)(row0 + r) * Kd + k0 + c4 * 8;
            const long long gb = (long long)(col0 + r) * Kd + k0 + c4 * 8;
            cp16(sb + soff,                  Ah + ga);
            cp16(sb + 1 * TILE_BYTES + soff, Al + ga);
            cp16(sb + 2 * TILE_BYTES + soff, Bh + gb);
            if (NPROD == 3) cp16(sb + 3 * TILE_BYTES + soff, Bl + gb);
        }
        asm volatile("cp.async.commit_group;" ::: "memory");
    };

    auto compute_stage = [&](int st) {
        const uint32_t sb  = sbase + (uint32_t)st * STAGE_BYTES;
        const uint32_t aoh = sb + a_off;
        const uint32_t aol = aoh + TILE_BYTES;
        const uint32_t boh = sb + 2 * TILE_BYTES + b_off;
        const uint32_t bol = boh + TILE_BYTES;
#pragma unroll
        for (int kk = 0; kk < 2; kk++) {
            uint32_t ahf[4][4], alf[4][4], bhf[4][2], blf[4][2];
#pragma unroll
            for (int mi = 0; mi < 4; mi++) ldm_x4(ahf[mi], aoh + mi * 1280 + kk * 32);
#pragma unroll
            for (int mi = 0; mi < 4; mi++) ldm_x4(alf[mi], aol + mi * 1280 + kk * 32);
#pragma unroll
            for (int ni = 0; ni < 4; ni++) ldm_x2(bhf[ni], boh + ni * 640 + kk * 32);
            if (NPROD == 3) {
#pragma unroll
                for (int ni = 0; ni < 4; ni++) ldm_x2(blf[ni], bol + ni * 640 + kk * 32);
            }
#pragma unroll
            for (int mi = 0; mi < 4; mi++)
#pragma unroll
                for (int ni = 0; ni < 4; ni++) mma16816(acc[mi][ni], ahf[mi], bhf[ni]);
#pragma unroll
            for (int mi = 0; mi < 4; mi++)
#pragma unroll
                for (int ni = 0; ni < 4; ni++) mma16816(acc[mi][ni], alf[mi], bhf[ni]);
            if (NPROD == 3) {
#pragma unroll
                for (int mi = 0; mi < 4; mi++)
#pragma unroll
                    for (int ni = 0; ni < 4; ni++) mma16816(acc[mi][ni], ahf[mi], blf[ni]);
            }
        }
    };

    const int nc = Kd / KC;
    load_stage(0, 0);
    load_stage(1, 1);

    for (int c = 0; c < nc; c++) {
        if (c + 2 < nc) asm volatile("cp.async.wait_group 1;" ::: "memory");
        else            asm volatile("cp.async.wait_group 0;" ::: "memory");
        __syncthreads();
        compute_stage(c % N_STAGES);
        if (c + 2 < nc) load_stage((c + 2) % N_STAGES, c + 2);
    }

    // ---- epilogue ----
#pragma unroll
    for (int mi = 0; mi < 4; mi++) {
        const long long r = row0 + mbase + mi * 16 + g;
#pragma unroll
        for (int ni = 0; ni < 4; ni++) {
            const int cc = col0 + nbase + ni * 8 + t * 2;
            float2 v0, v1;
            v0.x = acc[mi][ni][0]; v0.y = acc[mi][ni][1];
            v1.x = acc[mi][ni][2]; v1.y = acc[mi][ni][3];
            if (BIAS) {
                const float2 bv = *(const float2*)(bias + cc);
                v0.x += bv.x; v0.y += bv.y;
                v1.x += bv.x; v1.y += bv.y;
            }
            if (RELU) {
                v0.x = fmaxf(v0.x, 0.f); v0.y = fmaxf(v0.y, 0.f);
                v1.x = fmaxf(v1.x, 0.f); v1.y = fmaxf(v1.y, 0.f);
            }
            if (OM == 0) {
                float* Cz = C + z * sC;
                *(float2*)(Cz + r * Nn + cc)       = v0;
                *(float2*)(Cz + (r + 8) * Nn + cc) = v1;
            } else {
                __half* Chz = Ch + z * sC;
                __half* Clz = Cl + z * sC;
                __half h0, h1, l0, l1;
                split1(v0.x, h0, l0); split1(v0.y, h1, l1);
                *(uint32_t*)(Chz + r * Nn + cc) = pack2(h0, h1);
                *(uint32_t*)(Clz + r * Nn + cc) = pack2(l0, l1);
                split1(v1.x, h0, l0); split1(v1.y, h1, l1);
                *(uint32_t*)(Chz + (r + 8) * Nn + cc) = pack2(h0, h1);
                *(uint32_t*)(Clz + (r + 8) * Nn + cc) = pack2(l0, l1);
            }
        }
    }
}

// ---------------------------------------------------------------------------
// fp32 -> fp16 hi/lo elementwise split
// ---------------------------------------------------------------------------
__global__ __launch_bounds__(256)
void split_kernel(const float* __restrict__ in, __half* __restrict__ oh,
                  __half* __restrict__ ol, long long n4)
{
    long long i = (long long)blockIdx.x * blockDim.x + threadIdx.x;
    if (i >= n4) return;
    float4 v = ((const float4*)in)[i];
    __half h0, h1, h2, h3, l0, l1, l2, l3;
    split1(v.x, h0, l0); split1(v.y, h1, l1);
    split1(v.z, h2, l2); split1(v.w, h3, l3);
    uint2 hv, lv;
    hv.x = pack2(h0, h1); hv.y = pack2(h2, h3);
    lv.x = pack2(l0, l1); lv.y = pack2(l2, l3);
    ((uint2*)oh)[i] = hv;
    ((uint2*)ol)[i] = lv;
}

// ---------------------------------------------------------------------------
// fp32 [R,C] -> transposed fp16 hi/lo [C,R] (batched via blockIdx.z)
// ---------------------------------------------------------------------------
__global__ __launch_bounds__(256)
void tsplit_kernel(const float* __restrict__ in, __half* __restrict__ oh,
                   __half* __restrict__ ol, int R, int C)
{
    __shared__ float t[32][33];
    const long long zoff = (long long)blockIdx.z * R * C;
    in += zoff; oh += zoff; ol += zoff;
    const int tx = threadIdx.x, ty = threadIdx.y;
    const int x = blockIdx.x * 32 + tx;
    const int y0 = blockIdx.y * 32 + ty;
#pragma unroll
    for (int i = 0; i < 32; i += 8)
        t[ty + i][tx] = in[(long long)(y0 + i) * C + x];
    __syncthreads();
    const int ox = blockIdx.y * 32 + tx;
    const int oy0 = blockIdx.x * 32 + ty;
#pragma unroll
    for (int i = 0; i < 32; i += 8) {
        float v = t[tx][ty + i];
        __half h, l;
        split1(v, h, l);
        oh[(long long)(oy0 + i) * R + ox] = h;
        ol[(long long)(oy0 + i) * R + ox] = l;
    }
}

// ---------------------------------------------------------------------------
// warp-per-row matvec: out[r] = sum_c Mrow[r,:]*v[:]   (C = D_EMB)
// ---------------------------------------------------------------------------
__inline__ __device__ float warpSum(float v) {
#pragma unroll
    for (int o = 16; o > 0; o >>= 1) v += __shfl_xor_sync(0xffffffffu, v, o);
    return v;
}
__inline__ __device__ float warpMax(float v) {
#pragma unroll
    for (int o = 16; o > 0; o >>= 1) v = fmaxf(v, __shfl_xor_sync(0xffffffffu, v, o));
    return v;
}

__global__ __launch_bounds__(256)
void matvec_kernel(const float* __restrict__ Mrow, const float* __restrict__ v,
                   float* __restrict__ out)
{
    const int row  = blockIdx.x * 8 + (threadIdx.x >> 5);
    const int lane = threadIdx.x & 31;
    const float* R = Mrow + (long long)row * D_EMB;
    float s = 0.f;
#pragma unroll
    for (int d = lane * 4; d < D_EMB; d += 128) {
        const float4 a = *(const float4*)(R + d);
        const float4 b = *(const float4*)(v + d);
        s += a.x * b.x + a.y * b.y + a.z * b.z + a.w * b.w;
    }
    s = warpSum(s);
    if (lane == 0) out[row] = s;
}

// ---------------------------------------------------------------------------
// Row softmax over 2048 fp32 (+ per-i offset w) -> fp16 hi/lo outputs
// ---------------------------------------------------------------------------
__global__ __launch_bounds__(256)
void softmax_split(const float* __restrict__ S, const float* __restrict__ w,
                   __half* __restrict__ ah, __half* __restrict__ al)
{
    const long long base = (long long)blockIdx.x * N_SEQ;
    const float* row = S + base;
    const float* wb  = w + (long long)(blockIdx.x >> 11) * N_SEQ;  // batch = blk / 2048
    const int tid = threadIdx.x;
    const int lane = tid & 31;
    const int wid = tid >> 5;

    float4 v0 = ((const float4*)row)[tid];
    float4 v1 = ((const float4*)row)[tid + 256];
    const float4 w0 = ((const float4*)wb)[tid];
    const float4 w1 = ((const float4*)wb)[tid + 256];
    v0.x += w0.x; v0.y += w0.y; v0.z += w0.z; v0.w += w0.w;
    v1.x += w1.x; v1.y += w1.y; v1.z += w1.z; v1.w += w1.w;

    __shared__ float sm[8];
    float m = fmaxf(fmaxf(fmaxf(v0.x, v0.y), fmaxf(v0.z, v0.w)),
                    fmaxf(fmaxf(v1.x, v1.y), fmaxf(v1.z, v1.w)));
    m = warpMax(m);
    if (lane == 0) sm[wid] = m;
    __syncthreads();
    if (wid == 0) {
        float t = (lane < 8) ? sm[lane] : -3.402823e38f;
        t = warpMax(t);
        if (lane == 0) sm[0] = t;
    }
    __syncthreads();
    m = sm[0];
    __syncthreads();

    v0.x = expf(v0.x - m); v0.y = expf(v0.y - m);
    v0.z = expf(v0.z - m); v0.w = expf(v0.w - m);
    v1.x = expf(v1.x - m); v1.y = expf(v1.y - m);
    v1.z = expf(v1.z - m); v1.w = expf(v1.w - m);

    float s = (v0.x + v0.y + v0.z + v0.w) + (v1.x + v1.y + v1.z + v1.w);
    s = warpSum(s);
    if (lane == 0) sm[wid] = s;
    __syncthreads();
    if (wid == 0) {
        float t = (lane < 8) ? sm[lane] : 0.f;
        t = warpSum(t);
        if (lane == 0) sm[0] = t;
    }
    __syncthreads();
    const float inv = 1.0f / sm[0];

    __half h0, h1, h2, h3, l0, l1, l2, l3;
    uint2 hv, lv;
    split1(v0.x * inv, h0, l0); split1(v0.y * inv, h1, l1);
    split1(v0.z * inv, h2, l2); split1(v0.w * inv, h3, l3);
    hv.x = pack2(h0, h1); hv.y = pack2(h2, h3);
    lv.x = pack2(l0, l1); lv.y = pack2(l2, l3);
    ((uint2*)(ah + base))[tid] = hv;
    ((uint2*)(al + base))[tid] = lv;

    split1(v1.x * inv, h0, l0); split1(v1.y * inv, h1, l1);
    split1(v1.z * inv, h2, l2); split1(v1.w * inv, h3, l3);
    hv.x = pack2(h0, h1); hv.y = pack2(h2, h3);
    lv.x = pack2(l0, l1); lv.y = pack2(l2, l3);
    ((uint2*)(ah + base))[tid + 256] = hv;
    ((uint2*)(al + base))[tid + 256] = lv;
}

// ---------------------------------------------------------------------------
extern "C" void kernel_launch(void* const* d_in, const int* in_sizes, int n_in,
                              void* d_out, int out_size)
{
    const float* x  = (const float*)d_in[0];
    const float* Wq = (const float*)d_in[1];
    const float* bq = (const float*)d_in[2];
    const float* Wk = (const float*)d_in[3];
    const float* bk = (const float*)d_in[4];
    const float* Wv = (const float*)d_in[5];
    const float* bv = (const float*)d_in[6];
    const float* Wm = (const float*)d_in[7];
    const float* bm = (const float*)d_in[8];
    float* out = (float*)d_out;
    (void)bq;  // bq enters scores only via terms constant along the softmax axis

    __half *xh, *xl, *Wqh, *Wql, *Wkh, *Wkl, *Wvh, *Wvl, *Wmh, *Wml;
    __half *M2h, *M2l, *Zh, *Zl, *Vth, *Vtl, *Th, *Tl, *ah, *al;
    float *Vf, *S, *wv, *w;
    cudaGetSymbolAddress((void**)&xh, g_xh);   cudaGetSymbolAddress((void**)&xl, g_xl);
    cudaGetSymbolAddress((void**)&Wqh, g_Wqh); cudaGetSymbolAddress((void**)&Wql, g_Wql);
    cudaGetSymbolAddress((void**)&Wkh, g_Wkh); cudaGetSymbolAddress((void**)&Wkl, g_Wkl);
    cudaGetSymbolAddress((void**)&Wvh, g_Wvh); cudaGetSymbolAddress((void**)&Wvl, g_Wvl);
    cudaGetSymbolAddress((void**)&Wmh, g_Wmh); cudaGetSymbolAddress((void**)&Wml, g_Wml);
    cudaGetSymbolAddress((void**)&M2h, g_M2h); cudaGetSymbolAddress((void**)&M2l, g_M2l);
    cudaGetSymbolAddress((void**)&Zh, g_Zh);   cudaGetSymbolAddress((void**)&Zl, g_Zl);
    cudaGetSymbolAddress((void**)&Vf, g_Vf);
    cudaGetSymbolAddress((void**)&Vth, g_Vth); cudaGetSymbolAddress((void**)&Vtl, g_Vtl);
    cudaGetSymbolAddress((void**)&Th, g_Th);   cudaGetSymbolAddress((void**)&Tl, g_Tl);
    cudaGetSymbolAddress((void**)&ah, g_ah);   cudaGetSymbolAddress((void**)&al, g_al);
    cudaGetSymbolAddress((void**)&S, g_S);
    cudaGetSymbolAddress((void**)&wv, g_wv);   cudaGetSymbolAddress((void**)&w, g_w);

    cudaFuncSetAttribute(gemm_mma<3, 1, false, false>,
                         cudaFuncAttributeMaxDynamicSharedMemorySize, SMEM_BYTES);
    cudaFuncSetAttribute(gemm_mma<3, 0, false, false>,
                         cudaFuncAttributeMaxDynamicSharedMemorySize, SMEM_BYTES);
    cudaFuncSetAttribute(gemm_mma<2, 0, true, false>,
                         cudaFuncAttributeMaxDynamicSharedMemorySize, SMEM_BYTES);
    cudaFuncSetAttribute(gemm_mma<2, 1, false, false>,
                         cudaFuncAttributeMaxDynamicSharedMemorySize, SMEM_BYTES);
    cudaFuncSetAttribute(gemm_mma<2, 0, true, true>,
                         cudaFuncAttributeMaxDynamicSharedMemorySize, SMEM_BYTES);

    const long long nX = (long long)BN_TOT * D_EMB;
    const long long nW = (long long)D_EMB * D_EMB;

    // 1) split x (plain); split Wq, Wk (plain, K-contiguous rows)
    split_kernel<<<(unsigned)((nX / 4 + 255) / 256), 256>>>(x, xh, xl, nX / 4);
    split_kernel<<<(unsigned)((nW / 4 + 255) / 256), 256>>>(Wq, Wqh, Wql, nW / 4);
    split_kernel<<<(unsigned)((nW / 4 + 255) / 256), 256>>>(Wk, Wkh, Wkl, nW / 4);

    // 2) transpose-split Wv, Wm (used as [n,k] B operands)
    {
        dim3 g(D_EMB / 32, D_EMB / 32, 1), b(32, 8);
        tsplit_kernel<<<g, b>>>(Wv, Wvh, Wvl, D_EMB, D_EMB);
        tsplit_kernel<<<g, b>>>(Wm, Wmh, Wml, D_EMB, D_EMB);
    }

    // 3) M2[f,e] = sum_d Wq[f,d]*Wk[e,d], 3-MMA, split epilogue
    {
        dim3 g(D_EMB / 128, D_EMB / 128, 1);
        gemm_mma<3, 1, false, false><<<g, 256, SMEM_BYTES>>>(
            Wqh, Wql, Wkh, Wkl, nullptr, nullptr, M2h, M2l, D_EMB, D_EMB, 0, 0, 0);
    }

    // 4) bias correction vector: wv = Wq*bk ; w = x*wv  (exact rank-1 term)
    matvec_kernel<<<D_EMB / 8, 256>>>(Wq, bk, wv);
    matvec_kernel<<<BN_TOT / 8, 256>>>(x, wv, w);

    // 5) V projection (2-MMA): V = x @ Wv + bv (fp32), then transpose-split
    {
        dim3 g(D_EMB / 128, BN_TOT / 128, 1);
        gemm_mma<2, 0, true, false><<<g, 256, SMEM_BYTES>>>(
            xh, xl, Wvh, nullptr, bv, Vf, nullptr, nullptr, D_EMB, D_EMB, 0, 0, 0);
        dim3 gt(D_EMB / 32, N_SEQ / 32, N_BATCH), bt(32, 8);
        tsplit_kernel<<<gt, bt>>>(Vf, Vth, Vtl, N_SEQ, D_EMB);
    }

    // 6) Z = x @ M  (3-MMA, split epilogue)
    {
        dim3 g(D_EMB / 128, BN_TOT / 128, 1);
        gemm_mma<3, 1, false, false><<<g, 256, SMEM_BYTES>>>(
            xh, xl, M2h, M2l, nullptr, nullptr, Zh, Zl, D_EMB, D_EMB, 0, 0, 0);
    }

    // 7) S'[b,j,i] = Z_b[j,:] . x_b[i,:]  (3-MMA, M=N=2048, K=1024, batched)
    {
        dim3 g(N_SEQ / 128, N_SEQ / 128, N_BATCH);
        gemm_mma<3, 0, false, false><<<g, 256, SMEM_BYTES>>>(
            Zh, Zl, xh, xl, nullptr, S, nullptr, nullptr, N_SEQ, D_EMB,
            (long long)N_SEQ * D_EMB, (long long)N_SEQ * D_EMB,
            (long long)N_SEQ * N_SEQ);
    }

    // 8) row softmax (with +w_i offset) -> alpha hi/lo
    softmax_split<<<BN_TOT, 256>>>(S, w, ah, al);

    // 9) T[b] = alpha'_b @ V_b via Vt (2-MMA, B = Vth only), split epilogue
    {
        dim3 g(D_EMB / 128, N_SEQ / 128, N_BATCH);
        gemm_mma<2, 1, false, false><<<g, 256, SMEM_BYTES>>>(
            ah, al, Vth, nullptr, nullptr, nullptr, Th, Tl, D_EMB, N_SEQ,
            (long long)N_SEQ * N_SEQ, (long long)D_EMB * N_SEQ,
            (long long)N_SEQ * D_EMB);
    }

    // 10) out = relu(T @ Wm + bm)  (2-MMA, B = Wmh only)
    {
        dim3 g(D_EMB / 128, BN_TOT / 128, 1);
        gemm_mma<2, 0, true, true><<<g, 256, SMEM_BYTES>>>(
            Th, Tl, Wmh, nullptr, bm, out, nullptr, nullptr, D_EMB, D_EMB, 0, 0, 0);
    }
}

// round 8
// speedup vs baseline: 3.3343x; 1.0565x over previous
#include <cuda_runtime.h>
#include <cuda_fp16.h>
#include <stdint.h>
#include <math.h>

#define D_EMB   1024
#define N_BATCH 4
#define N_SEQ   2048
#define BN_TOT  (N_BATCH * N_SEQ)   // 8192

// ---------------------------------------------------------------------------
// Device scratch (allocation-free per harness rules)
// ---------------------------------------------------------------------------
__device__ __half g_xh[BN_TOT * D_EMB], g_xl[BN_TOT * D_EMB];
__device__ __half g_Wqh[D_EMB * D_EMB], g_Wql[D_EMB * D_EMB];  // plain split
__device__ __half g_Wkh[D_EMB * D_EMB], g_Wkl[D_EMB * D_EMB];  // plain split
__device__ __half g_Wvh[D_EMB * D_EMB], g_Wvl[D_EMB * D_EMB];  // transposed split
__device__ __half g_Wmh[D_EMB * D_EMB], g_Wml[D_EMB * D_EMB];  // transposed split
__device__ __half g_M2h[D_EMB * D_EMB], g_M2l[D_EMB * D_EMB];  // Wq*Wk^T
__device__ __half g_Zh[BN_TOT * D_EMB], g_Zl[BN_TOT * D_EMB];  // x*M
__device__ float g_Vf[BN_TOT * D_EMB];
__device__ __half g_Vth[BN_TOT * D_EMB], g_Vtl[BN_TOT * D_EMB];
__device__ __half g_Th[BN_TOT * D_EMB], g_Tl[BN_TOT * D_EMB];
__device__ float g_S[(size_t)N_BATCH * N_SEQ * N_SEQ];
__device__ __half g_ah[(size_t)N_BATCH * N_SEQ * N_SEQ];
__device__ __half g_al[(size_t)N_BATCH * N_SEQ * N_SEQ];
__device__ float g_wv[D_EMB];     // Wq * bk
__device__ float g_w[BN_TOT];     // x * (Wq*bk)  -- per-query softmax offset

// ---------------------------------------------------------------------------
// helpers
// ---------------------------------------------------------------------------
__device__ __forceinline__ uint32_t smem_u32(const void* p) {
    uint32_t a;
    asm("{ .reg .u64 t; cvta.to.shared.u64 t, %1; cvt.u32.u64 %0, t; }"
        : "=r"(a) : "l"(p));
    return a;
}
__device__ __forceinline__ uint64_t gptr64(const void* p) {
    uint64_t g;
    asm("cvta.to.global.u64 %0, %1;" : "=l"(g) : "l"(p));
    return g;
}
__device__ __forceinline__ void cp16(uint32_t saddr, const void* g) {
    asm volatile("cp.async.cg.shared.global [%0], [%1], 16;"
                 :: "r"(saddr), "l"(gptr64(g)) : "memory");
}

// warp-level fp16 MMA, fp32 accumulate (fallback HMMA on sm_103)
__device__ __forceinline__ void mma16816(float* c, const uint32_t* a, const uint32_t* b) {
    asm volatile(
        "mma.sync.aligned.m16n8k16.row.col.f32.f16.f16.f32 "
        "{%0,%1,%2,%3}, {%4,%5,%6,%7}, {%8,%9}, {%0,%1,%2,%3};"
        : "+f"(c[0]), "+f"(c[1]), "+f"(c[2]), "+f"(c[3])
        : "r"(a[0]), "r"(a[1]), "r"(a[2]), "r"(a[3]), "r"(b[0]), "r"(b[1]));
}
__device__ __forceinline__ void ldm_x4(uint32_t* r, uint32_t addr) {
    asm volatile("ldmatrix.sync.aligned.m8n8.x4.shared.b16 {%0,%1,%2,%3}, [%4];"
                 : "=r"(r[0]), "=r"(r[1]), "=r"(r[2]), "=r"(r[3]) : "r"(addr));
}
// NON-transposed x2: correct for B stored [N,K] row-major (K-contiguous)
__device__ __forceinline__ void ldm_x2(uint32_t* r, uint32_t addr) {
    asm volatile("ldmatrix.sync.aligned.m8n8.x2.shared.b16 {%0,%1}, [%2];"
                 : "=r"(r[0]), "=r"(r[1]) : "r"(addr));
}

__device__ __forceinline__ void split1(float v, __half& h, __half& l) {
    h = __float2half(v);
    l = __float2half(v - __half2float(h));
}
__device__ __forceinline__ uint32_t pack2(__half a, __half b) {
    __half2 t; t.x = a; t.y = b;
    return *reinterpret_cast<uint32_t*>(&t);
}

// smem geometry: rows padded to 40 fp16 (80B) -> conflict-free ldmatrix
#define KC          32
#define ROW_PAD     40
#define A_TILE_BYTES (128 * ROW_PAD * 2)         // 10240
#define B_TILE_BYTES (256 * ROW_PAD * 2)         // 20480
// stage layout: Ah | Al | Bh | Bl
#define OFF_AL      A_TILE_BYTES                 // 10240
#define OFF_BH      (2 * A_TILE_BYTES)           // 20480
#define OFF_BL      (2 * A_TILE_BYTES + B_TILE_BYTES)  // 40960
#define STAGE_BYTES (2 * A_TILE_BYTES + 2 * B_TILE_BYTES)  // 61440
#define N_STAGES    3
#define SMEM_BYTES  (N_STAGES * STAGE_BYTES)     // 184320

// ---------------------------------------------------------------------------
// NT GEMM: C = (Ah+Al)[M,K] @ (Bh+Bl)[N,K]^T, fp16 split.
// NPROD=3: hh + lh + hl (near-fp32). NPROD=2: hh + lh (B_lo never loaded).
// CTA 128x256, 8 warps (2x4), warp tile 64x64, 3-stage cp.async pipeline.
// OM=0: fp32 C output; OM=1: fp16 hi/lo split output (Ch, Cl).
// M mult of 128, N mult of 256, K mult of 32.
// ---------------------------------------------------------------------------
template <int NPROD, int OM, bool BIAS, bool RELU>
__global__ __launch_bounds__(256, 1)
void gemm_mma(const __half* __restrict__ Ah, const __half* __restrict__ Al,
              const __half* __restrict__ Bh, const __half* __restrict__ Bl,
              const float* __restrict__ bias, float* __restrict__ C,
              __half* __restrict__ Ch, __half* __restrict__ Cl,
              int Nn, int Kd, long long sA, long long sB, long long sC)
{
    extern __shared__ __align__(128) char smem[];
    const int tid = threadIdx.x;
    const long long z = blockIdx.z;
    Ah += z * sA; Al += z * sA;
    Bh += z * sB;
    if (NPROD == 3) Bl += z * sB;
    const int row0 = blockIdx.y * 128;
    const int col0 = blockIdx.x * 256;

    const int warp  = tid >> 5;
    const int lane  = tid & 31;
    const int g     = lane >> 2;
    const int t     = lane & 3;
    const int mbase = (warp & 1) * 64;      // 2 row-groups
    const int nbase = (warp >> 1) * 64;     // 4 col-groups

    const uint32_t sbase = smem_u32(smem);

    const uint32_t a_off = (uint32_t)(((mbase + (lane & 15)) * ROW_PAD + (lane >> 4) * 8) * 2);
    const uint32_t b_off = (uint32_t)(((nbase + (lane & 7)) * ROW_PAD + ((lane >> 3) & 1) * 8) * 2);

    float acc[4][8][4];
#pragma unroll
    for (int mi = 0; mi < 4; mi++)
#pragma unroll
        for (int ni = 0; ni < 8; ni++)
#pragma unroll
            for (int r = 0; r < 4; r++) acc[mi][ni][r] = 0.f;

    // per stage: A 512 cp x2, B 1024 cp x(NPROD-1 for Bl)
    auto load_stage = [&](int st, int kc) {
        const uint32_t sb = sbase + (uint32_t)st * STAGE_BYTES;
        const int k0 = kc * KC;
#pragma unroll
        for (int i = 0; i < 2; i++) {       // A hi + lo: 512 cp each
            const int idx = tid + (i << 8);
            const int r  = idx >> 2;
            const int c4 = idx & 3;
            const uint32_t soff = (uint32_t)(r * 80 + c4 * 16);
            const long long ga = (long long)(row0 + r) * Kd + k0 + c4 * 8;
            cp16(sb + soff,          Ah + ga);
            cp16(sb + OFF_AL + soff, Al + ga);
        }
#pragma unroll
        for (int i = 0; i < 4; i++) {       // B hi (+ lo): 1024 cp each
            const int idx = tid + (i << 8);
            const int r  = idx >> 2;
            const int c4 = idx & 3;
            const uint32_t soff = (uint32_t)(r * 80 + c4 * 16);
            const long long gb = (long long)(col0 + r) * Kd + k0 + c4 * 8;
            cp16(sb + OFF_BH + soff, Bh + gb);
            if (NPROD == 3) cp16(sb + OFF_BL + soff, Bl + gb);
        }
        asm volatile("cp.async.commit_group;" ::: "memory");
    };

    auto compute_stage = [&](int st) {
        const uint32_t sb  = sbase + (uint32_t)st * STAGE_BYTES;
        const uint32_t aoh = sb + a_off;
        const uint32_t aol = aoh + OFF_AL;
        const uint32_t boh = sb + OFF_BH + b_off;
        const uint32_t bol = boh + B_TILE_BYTES;
#pragma unroll
        for (int kk = 0; kk < 2; kk++) {
            uint32_t ahf[4][4], bhf[8][2];
            // hh sweep
#pragma unroll
            for (int mi = 0; mi < 4; mi++) ldm_x4(ahf[mi], aoh + mi * 1280 + kk * 32);
#pragma unroll
            for (int ni = 0; ni < 8; ni++) ldm_x2(bhf[ni], boh + ni * 640 + kk * 32);
#pragma unroll
            for (int mi = 0; mi < 4; mi++)
#pragma unroll
                for (int ni = 0; ni < 8; ni++) mma16816(acc[mi][ni], ahf[mi], bhf[ni]);
            // lh sweep (A_lo x B_hi)
            {
                uint32_t alf[4][4];
#pragma unroll
                for (int mi = 0; mi < 4; mi++) ldm_x4(alf[mi], aol + mi * 1280 + kk * 32);
#pragma unroll
                for (int mi = 0; mi < 4; mi++)
#pragma unroll
                    for (int ni = 0; ni < 8; ni++) mma16816(acc[mi][ni], alf[mi], bhf[ni]);
            }
            // hl sweep (A_hi x B_lo)
            if (NPROD == 3) {
                uint32_t blf[8][2];
#pragma unroll
                for (int ni = 0; ni < 8; ni++) ldm_x2(blf[ni], bol + ni * 640 + kk * 32);
#pragma unroll
                for (int mi = 0; mi < 4; mi++)
#pragma unroll
                    for (int ni = 0; ni < 8; ni++) mma16816(acc[mi][ni], ahf[mi], blf[ni]);
            }
        }
    };

    const int nc = Kd / KC;
    load_stage(0, 0);
    load_stage(1, 1);

    for (int c = 0; c < nc; c++) {
        if (c + 2 < nc) asm volatile("cp.async.wait_group 1;" ::: "memory");
        else            asm volatile("cp.async.wait_group 0;" ::: "memory");
        __syncthreads();
        compute_stage(c % N_STAGES);
        if (c + 2 < nc) load_stage((c + 2) % N_STAGES, c + 2);
    }

    // ---- epilogue ----
#pragma unroll
    for (int mi = 0; mi < 4; mi++) {
        const long long r = row0 + mbase + mi * 16 + g;
#pragma unroll
        for (int ni = 0; ni < 8; ni++) {
            const int cc = col0 + nbase + ni * 8 + t * 2;
            float2 v0, v1;
            v0.x = acc[mi][ni][0]; v0.y = acc[mi][ni][1];
            v1.x = acc[mi][ni][2]; v1.y = acc[mi][ni][3];
            if (BIAS) {
                const float2 bv = *(const float2*)(bias + cc);
                v0.x += bv.x; v0.y += bv.y;
                v1.x += bv.x; v1.y += bv.y;
            }
            if (RELU) {
                v0.x = fmaxf(v0.x, 0.f); v0.y = fmaxf(v0.y, 0.f);
                v1.x = fmaxf(v1.x, 0.f); v1.y = fmaxf(v1.y, 0.f);
            }
            if (OM == 0) {
                float* Cz = C + z * sC;
                *(float2*)(Cz + r * Nn + cc)       = v0;
                *(float2*)(Cz + (r + 8) * Nn + cc) = v1;
            } else {
                __half* Chz = Ch + z * sC;
                __half* Clz = Cl + z * sC;
                __half h0, h1, l0, l1;
                split1(v0.x, h0, l0); split1(v0.y, h1, l1);
                *(uint32_t*)(Chz + r * Nn + cc) = pack2(h0, h1);
                *(uint32_t*)(Clz + r * Nn + cc) = pack2(l0, l1);
                split1(v1.x, h0, l0); split1(v1.y, h1, l1);
                *(uint32_t*)(Chz + (r + 8) * Nn + cc) = pack2(h0, h1);
                *(uint32_t*)(Clz + (r + 8) * Nn + cc) = pack2(l0, l1);
            }
        }
    }
}

// ---------------------------------------------------------------------------
// fp32 -> fp16 hi/lo elementwise split
// ---------------------------------------------------------------------------
__global__ __launch_bounds__(256)
void split_kernel(const float* __restrict__ in, __half* __restrict__ oh,
                  __half* __restrict__ ol, long long n4)
{
    long long i = (long long)blockIdx.x * blockDim.x + threadIdx.x;
    if (i >= n4) return;
    float4 v = ((const float4*)in)[i];
    __half h0, h1, h2, h3, l0, l1, l2, l3;
    split1(v.x, h0, l0); split1(v.y, h1, l1);
    split1(v.z, h2, l2); split1(v.w, h3, l3);
    uint2 hv, lv;
    hv.x = pack2(h0, h1); hv.y = pack2(h2, h3);
    lv.x = pack2(l0, l1); lv.y = pack2(l2, l3);
    ((uint2*)oh)[i] = hv;
    ((uint2*)ol)[i] = lv;
}

// ---------------------------------------------------------------------------
// fp32 [R,C] -> transposed fp16 hi/lo [C,R] (batched via blockIdx.z)
// ---------------------------------------------------------------------------
__global__ __launch_bounds__(256)
void tsplit_kernel(const float* __restrict__ in, __half* __restrict__ oh,
                   __half* __restrict__ ol, int R, int C)
{
    __shared__ float t[32][33];
    const long long zoff = (long long)blockIdx.z * R * C;
    in += zoff; oh += zoff; ol += zoff;
    const int tx = threadIdx.x, ty = threadIdx.y;
    const int x = blockIdx.x * 32 + tx;
    const int y0 = blockIdx.y * 32 + ty;
#pragma unroll
    for (int i = 0; i < 32; i += 8)
        t[ty + i][tx] = in[(long long)(y0 + i) * C + x];
    __syncthreads();
    const int ox = blockIdx.y * 32 + tx;
    const int oy0 = blockIdx.x * 32 + ty;
#pragma unroll
    for (int i = 0; i < 32; i += 8) {
        float v = t[tx][ty + i];
        __half h, l;
        split1(v, h, l);
        oh[(long long)(oy0 + i) * R + ox] = h;
        ol[(long long)(oy0 + i) * R + ox] = l;
    }
}

// ---------------------------------------------------------------------------
// warp-per-row matvec: out[r] = sum_c Mrow[r,:]*v[:]   (C = D_EMB)
// ---------------------------------------------------------------------------
__inline__ __device__ float warpSum(float v) {
#pragma unroll
    for (int o = 16; o > 0; o >>= 1) v += __shfl_xor_sync(0xffffffffu, v, o);
    return v;
}
__inline__ __device__ float warpMax(float v) {
#pragma unroll
    for (int o = 16; o > 0; o >>= 1) v = fmaxf(v, __shfl_xor_sync(0xffffffffu, v, o));
    return v;
}

__global__ __launch_bounds__(256)
void matvec_kernel(const float* __restrict__ Mrow, const float* __restrict__ v,
                   float* __restrict__ out)
{
    const int row  = blockIdx.x * 8 + (threadIdx.x >> 5);
    const int lane = threadIdx.x & 31;
    const float* R = Mrow + (long long)row * D_EMB;
    float s = 0.f;
#pragma unroll
    for (int d = lane * 4; d < D_EMB; d += 128) {
        const float4 a = *(const float4*)(R + d);
        const float4 b = *(const float4*)(v + d);
        s += a.x * b.x + a.y * b.y + a.z * b.z + a.w * b.w;
    }
    s = warpSum(s);
    if (lane == 0) out[row] = s;
}

// ---------------------------------------------------------------------------
// Row softmax over 2048 fp32 (+ per-i offset w) -> fp16 hi/lo outputs
// ---------------------------------------------------------------------------
__global__ __launch_bounds__(256)
void softmax_split(const float* __restrict__ S, const float* __restrict__ w,
                   __half* __restrict__ ah, __half* __restrict__ al)
{
    const long long base = (long long)blockIdx.x * N_SEQ;
    const float* row = S + base;
    const float* wb  = w + (long long)(blockIdx.x >> 11) * N_SEQ;  // batch = blk / 2048
    const int tid = threadIdx.x;
    const int lane = tid & 31;
    const int wid = tid >> 5;

    float4 v0 = ((const float4*)row)[tid];
    float4 v1 = ((const float4*)row)[tid + 256];
    const float4 w0 = ((const float4*)wb)[tid];
    const float4 w1 = ((const float4*)wb)[tid + 256];
    v0.x += w0.x; v0.y += w0.y; v0.z += w0.z; v0.w += w0.w;
    v1.x += w1.x; v1.y += w1.y; v1.z += w1.z; v1.w += w1.w;

    __shared__ float sm[8];
    float m = fmaxf(fmaxf(fmaxf(v0.x, v0.y), fmaxf(v0.z, v0.w)),
                    fmaxf(fmaxf(v1.x, v1.y), fmaxf(v1.z, v1.w)));
    m = warpMax(m);
    if (lane == 0) sm[wid] = m;
    __syncthreads();
    if (wid == 0) {
        float t = (lane < 8) ? sm[lane] : -3.402823e38f;
        t = warpMax(t);
        if (lane == 0) sm[0] = t;
    }
    __syncthreads();
    m = sm[0];
    __syncthreads();

    v0.x = expf(v0.x - m); v0.y = expf(v0.y - m);
    v0.z = expf(v0.z - m); v0.w = expf(v0.w - m);
    v1.x = expf(v1.x - m); v1.y = expf(v1.y - m);
    v1.z = expf(v1.z - m); v1.w = expf(v1.w - m);

    float s = (v0.x + v0.y + v0.z + v0.w) + (v1.x + v1.y + v1.z + v1.w);
    s = warpSum(s);
    if (lane == 0) sm[wid] = s;
    __syncthreads();
    if (wid == 0) {
        float t = (lane < 8) ? sm[lane] : 0.f;
        t = warpSum(t);
        if (lane == 0) sm[0] = t;
    }
    __syncthreads();
    const float inv = 1.0f / sm[0];

    __half h0, h1, h2, h3, l0, l1, l2, l3;
    uint2 hv, lv;
    split1(v0.x * inv, h0, l0); split1(v0.y * inv, h1, l1);
    split1(v0.z * inv, h2, l2); split1(v0.w * inv, h3, l3);
    hv.x = pack2(h0, h1); hv.y = pack2(h2, h3);
    lv.x = pack2(l0, l1); lv.y = pack2(l2, l3);
    ((uint2*)(ah + base))[tid] = hv;
    ((uint2*)(al + base))[tid] = lv;

    split1(v1.x * inv, h0, l0); split1(v1.y * inv, h1, l1);
    split1(v1.z * inv, h2, l2); split1(v1.w * inv, h3, l3);
    hv.x = pack2(h0, h1); hv.y = pack2(h2, h3);
    lv.x = pack2(l0, l1); lv.y = pack2(l2, l3);
    ((uint2*)(ah + base))[tid + 256] = hv;
    ((uint2*)(al + base))[tid + 256] = lv;
}

// ---------------------------------------------------------------------------
extern "C" void kernel_launch(void* const* d_in, const int* in_sizes, int n_in,
                              void* d_out, int out_size)
{
    const float* x  = (const float*)d_in[0];
    const float* Wq = (const float*)d_in[1];
    const float* bq = (const float*)d_in[2];
    const float* Wk = (const float*)d_in[3];
    const float* bk = (const float*)d_in[4];
    const float* Wv = (const float*)d_in[5];
    const float* bv = (const float*)d_in[6];
    const float* Wm = (const float*)d_in[7];
    const float* bm = (const float*)d_in[8];
    float* out = (float*)d_out;
    (void)bq;  // bq enters scores only via terms constant along the softmax axis

    __half *xh, *xl, *Wqh, *Wql, *Wkh, *Wkl, *Wvh, *Wvl, *Wmh, *Wml;
    __half *M2h, *M2l, *Zh, *Zl, *Vth, *Vtl, *Th, *Tl, *ah, *al;
    float *Vf, *S, *wv, *w;
    cudaGetSymbolAddress((void**)&xh, g_xh);   cudaGetSymbolAddress((void**)&xl, g_xl);
    cudaGetSymbolAddress((void**)&Wqh, g_Wqh); cudaGetSymbolAddress((void**)&Wql, g_Wql);
    cudaGetSymbolAddress((void**)&Wkh, g_Wkh); cudaGetSymbolAddress((void**)&Wkl, g_Wkl);
    cudaGetSymbolAddress((void**)&Wvh, g_Wvh); cudaGetSymbolAddress((void**)&Wvl, g_Wvl);
    cudaGetSymbolAddress((void**)&Wmh, g_Wmh); cudaGetSymbolAddress((void**)&Wml, g_Wml);
    cudaGetSymbolAddress((void**)&M2h, g_M2h); cudaGetSymbolAddress((void**)&M2l, g_M2l);
    cudaGetSymbolAddress((void**)&Zh, g_Zh);   cudaGetSymbolAddress((void**)&Zl, g_Zl);
    cudaGetSymbolAddress((void**)&Vf, g_Vf);
    cudaGetSymbolAddress((void**)&Vth, g_Vth); cudaGetSymbolAddress((void**)&Vtl, g_Vtl);
    cudaGetSymbolAddress((void**)&Th, g_Th);   cudaGetSymbolAddress((void**)&Tl, g_Tl);
    cudaGetSymbolAddress((void**)&ah, g_ah);   cudaGetSymbolAddress((void**)&al, g_al);
    cudaGetSymbolAddress((void**)&S, g_S);
    cudaGetSymbolAddress((void**)&wv, g_wv);   cudaGetSymbolAddress((void**)&w, g_w);

    cudaFuncSetAttribute(gemm_mma<3, 1, false, false>,
                         cudaFuncAttributeMaxDynamicSharedMemorySize, SMEM_BYTES);
    cudaFuncSetAttribute(gemm_mma<3, 0, false, false>,
                         cudaFuncAttributeMaxDynamicSharedMemorySize, SMEM_BYTES);
    cudaFuncSetAttribute(gemm_mma<2, 0, true, false>,
                         cudaFuncAttributeMaxDynamicSharedMemorySize, SMEM_BYTES);
    cudaFuncSetAttribute(gemm_mma<2, 1, false, false>,
                         cudaFuncAttributeMaxDynamicSharedMemorySize, SMEM_BYTES);
    cudaFuncSetAttribute(gemm_mma<2, 0, true, true>,
                         cudaFuncAttributeMaxDynamicSharedMemorySize, SMEM_BYTES);

    const long long nX = (long long)BN_TOT * D_EMB;
    const long long nW = (long long)D_EMB * D_EMB;

    // 1) split x (plain); split Wq, Wk (plain, K-contiguous rows)
    split_kernel<<<(unsigned)((nX / 4 + 255) / 256), 256>>>(x, xh, xl, nX / 4);
    split_kernel<<<(unsigned)((nW / 4 + 255) / 256), 256>>>(Wq, Wqh, Wql, nW / 4);
    split_kernel<<<(unsigned)((nW / 4 + 255) / 256), 256>>>(Wk, Wkh, Wkl, nW / 4);

    // 2) transpose-split Wv, Wm (used as [n,k] B operands)
    {
        dim3 g(D_EMB / 32, D_EMB / 32, 1), b(32, 8);
        tsplit_kernel<<<g, b>>>(Wv, Wvh, Wvl, D_EMB, D_EMB);
        tsplit_kernel<<<g, b>>>(Wm, Wmh, Wml, D_EMB, D_EMB);
    }

    // 3) M2[f,e] = sum_d Wq[f,d]*Wk[e,d], 3-MMA, split epilogue
    {
        dim3 g(D_EMB / 256, D_EMB / 128, 1);
        gemm_mma<3, 1, false, false><<<g, 256, SMEM_BYTES>>>(
            Wqh, Wql, Wkh, Wkl, nullptr, nullptr, M2h, M2l, D_EMB, D_EMB, 0, 0, 0);
    }

    // 4) bias correction vector: wv = Wq*bk ; w = x*wv  (exact rank-1 term)
    matvec_kernel<<<D_EMB / 8, 256>>>(Wq, bk, wv);
    matvec_kernel<<<BN_TOT / 8, 256>>>(x, wv, w);

    // 5) V projection (2-MMA): V = x @ Wv + bv (fp32), then transpose-split
    {
        dim3 g(D_EMB / 256, BN_TOT / 128, 1);
        gemm_mma<2, 0, true, false><<<g, 256, SMEM_BYTES>>>(
            xh, xl, Wvh, nullptr, bv, Vf, nullptr, nullptr, D_EMB, D_EMB, 0, 0, 0);
        dim3 gt(D_EMB / 32, N_SEQ / 32, N_BATCH), bt(32, 8);
        tsplit_kernel<<<gt, bt>>>(Vf, Vth, Vtl, N_SEQ, D_EMB);
    }

    // 6) Z = x @ M  (3-MMA, split epilogue)
    {
        dim3 g(D_EMB / 256, BN_TOT / 128, 1);
        gemm_mma<3, 1, false, false><<<g, 256, SMEM_BYTES>>>(
            xh, xl, M2h, M2l, nullptr, nullptr, Zh, Zl, D_EMB, D_EMB, 0, 0, 0);
    }

    // 7) S'[b,j,i] = Z_b[j,:] . x_b[i,:]  (3-MMA, M=N=2048, K=1024, batched)
    {
        dim3 g(N_SEQ / 256, N_SEQ / 128, N_BATCH);
        gemm_mma<3, 0, false, false><<<g, 256, SMEM_BYTES>>>(
            Zh, Zl, xh, xl, nullptr, S, nullptr, nullptr, N_SEQ, D_EMB,
            (long long)N_SEQ * D_EMB, (long long)N_SEQ * D_EMB,
            (long long)N_SEQ * N_SEQ);
    }

    // 8) row softmax (with +w_i offset) -> alpha hi/lo
    softmax_split<<<BN_TOT, 256>>>(S, w, ah, al);

    // 9) T[b] = alpha'_b @ V_b via Vt (2-MMA, B = Vth only), split epilogue
    {
        dim3 g(D_EMB / 256, N_SEQ / 128, N_BATCH);
        gemm_mma<2, 1, false, false><<<g, 256, SMEM_BYTES>>>(
            ah, al, Vth, nullptr, nullptr, nullptr, Th, Tl, D_EMB, N_SEQ,
            (long long)N_SEQ * N_SEQ, (long long)D_EMB * N_SEQ,
            (long long)N_SEQ * D_EMB);
    }

    // 10) out = relu(T @ Wm + bm)  (2-MMA, B = Wmh only)
    {
        dim3 g(D_EMB / 256, BN_TOT / 128, 1);
        gemm_mma<2, 0, true, true><<<g, 256, SMEM_BYTES>>>(
            Th, Tl, Wmh, nullptr, bm, out, nullptr, nullptr, D_EMB, D_EMB, 0, 0, 0);
    }
}

// round 9
// speedup vs baseline: 3.6473x; 1.0939x over previous
#include <cuda_runtime.h>
#include <cuda_fp16.h>
#include <stdint.h>
#include <math.h>

#define D_EMB   1024
#define N_BATCH 4
#define N_SEQ   2048
#define BN_TOT  (N_BATCH * N_SEQ)   // 8192

// ---------------------------------------------------------------------------
// Device scratch (allocation-free per harness rules)
// ---------------------------------------------------------------------------
__device__ __half g_xh[BN_TOT * D_EMB], g_xl[BN_TOT * D_EMB];
__device__ __half g_Wqh[D_EMB * D_EMB], g_Wql[D_EMB * D_EMB];  // plain split
__device__ __half g_Wkh[D_EMB * D_EMB], g_Wkl[D_EMB * D_EMB];  // plain split
__device__ __half g_Wvh[D_EMB * D_EMB], g_Wvl[D_EMB * D_EMB];  // transposed split
__device__ __half g_Wmh[D_EMB * D_EMB], g_Wml[D_EMB * D_EMB];  // transposed split
__device__ __half g_M2h[D_EMB * D_EMB], g_M2l[D_EMB * D_EMB];  // Wq*Wk^T
__device__ __half g_Zh[BN_TOT * D_EMB], g_Zl[BN_TOT * D_EMB];  // x*M
__device__ float g_Vf[BN_TOT * D_EMB];
__device__ __half g_Vth[BN_TOT * D_EMB], g_Vtl[BN_TOT * D_EMB];
__device__ __half g_Th[BN_TOT * D_EMB], g_Tl[BN_TOT * D_EMB];
__device__ float g_S[(size_t)N_BATCH * N_SEQ * N_SEQ];
__device__ __half g_ah[(size_t)N_BATCH * N_SEQ * N_SEQ];   // alpha hi only
__device__ float g_wv[D_EMB];     // Wq * bk
__device__ float g_w[BN_TOT];     // x * (Wq*bk)  -- per-query softmax offset

// ---------------------------------------------------------------------------
// helpers
// ---------------------------------------------------------------------------
__device__ __forceinline__ uint32_t smem_u32(const void* p) {
    uint32_t a;
    asm("{ .reg .u64 t; cvta.to.shared.u64 t, %1; cvt.u32.u64 %0, t; }"
        : "=r"(a) : "l"(p));
    return a;
}
__device__ __forceinline__ uint64_t gptr64(const void* p) {
    uint64_t g;
    asm("cvta.to.global.u64 %0, %1;" : "=l"(g) : "l"(p));
    return g;
}
__device__ __forceinline__ void cp16(uint32_t saddr, const void* g) {
    asm volatile("cp.async.cg.shared.global [%0], [%1], 16;"
                 :: "r"(saddr), "l"(gptr64(g)) : "memory");
}

// warp-level fp16 MMA, fp32 accumulate (fallback HMMA on sm_103)
__device__ __forceinline__ void mma16816(float* c, const uint32_t* a, const uint32_t* b) {
    asm volatile(
        "mma.sync.aligned.m16n8k16.row.col.f32.f16.f16.f32 "
        "{%0,%1,%2,%3}, {%4,%5,%6,%7}, {%8,%9}, {%0,%1,%2,%3};"
        : "+f"(c[0]), "+f"(c[1]), "+f"(c[2]), "+f"(c[3])
        : "r"(a[0]), "r"(a[1]), "r"(a[2]), "r"(a[3]), "r"(b[0]), "r"(b[1]));
}
__device__ __forceinline__ void ldm_x4(uint32_t* r, uint32_t addr) {
    asm volatile("ldmatrix.sync.aligned.m8n8.x4.shared.b16 {%0,%1,%2,%3}, [%4];"
                 : "=r"(r[0]), "=r"(r[1]), "=r"(r[2]), "=r"(r[3]) : "r"(addr));
}
// NON-transposed x2: correct for B stored [N,K] row-major (K-contiguous)
__device__ __forceinline__ void ldm_x2(uint32_t* r, uint32_t addr) {
    asm volatile("ldmatrix.sync.aligned.m8n8.x2.shared.b16 {%0,%1}, [%2];"
                 : "=r"(r[0]), "=r"(r[1]) : "r"(addr));
}

__device__ __forceinline__ void split1(float v, __half& h, __half& l) {
    h = __float2half(v);
    l = __float2half(v - __half2float(h));
}
__device__ __forceinline__ uint32_t pack2(__half a, __half b) {
    __half2 t; t.x = a; t.y = b;
    return *reinterpret_cast<uint32_t*>(&t);
}

// smem geometry: rows padded to 40 fp16 (80B) -> conflict-free ldmatrix
#define KC          32
#define ROW_PAD     40
#define A_TILE_BYTES (128 * ROW_PAD * 2)         // 10240
#define B_TILE_BYTES (256 * ROW_PAD * 2)         // 20480
// stage layout: Ah | Al | Bh | Bl
#define OFF_AL      A_TILE_BYTES                 // 10240
#define OFF_BH      (2 * A_TILE_BYTES)           // 20480
#define OFF_BL      (2 * A_TILE_BYTES + B_TILE_BYTES)  // 40960
#define STAGE_BYTES (2 * A_TILE_BYTES + 2 * B_TILE_BYTES)  // 61440
#define N_STAGES    3
#define SMEM_BYTES  (N_STAGES * STAGE_BYTES)     // 184320

// ---------------------------------------------------------------------------
// NT GEMM: C = (Ah+Al)[M,K] @ (Bh+Bl)[N,K]^T, fp16 split.
// NPROD=3: hh+lh+hl. NPROD=2: hh+lh (no B_lo). NPROD=1: hh only (no A_lo/B_lo).
// CTA 128x256, 8 warps (2x4), warp tile 64x64, 3-stage cp.async pipeline.
// OM=0: fp32 C output; OM=1: fp16 hi/lo split output (Ch, Cl).
// M mult of 128, N mult of 256, K mult of 32.
// ---------------------------------------------------------------------------
template <int NPROD, int OM, bool BIAS, bool RELU>
__global__ __launch_bounds__(256, 1)
void gemm_mma(const __half* __restrict__ Ah, const __half* __restrict__ Al,
              const __half* __restrict__ Bh, const __half* __restrict__ Bl,
              const float* __restrict__ bias, float* __restrict__ C,
              __half* __restrict__ Ch, __half* __restrict__ Cl,
              int Nn, int Kd, long long sA, long long sB, long long sC)
{
    extern __shared__ __align__(128) char smem[];
    const int tid = threadIdx.x;
    const long long z = blockIdx.z;
    Ah += z * sA;
    if (NPROD >= 2) Al += z * sA;
    Bh += z * sB;
    if (NPROD == 3) Bl += z * sB;
    const int row0 = blockIdx.y * 128;
    const int col0 = blockIdx.x * 256;

    const int warp  = tid >> 5;
    const int lane  = tid & 31;
    const int g     = lane >> 2;
    const int t     = lane & 3;
    const int mbase = (warp & 1) * 64;      // 2 row-groups
    const int nbase = (warp >> 1) * 64;     // 4 col-groups

    const uint32_t sbase = smem_u32(smem);

    const uint32_t a_off = (uint32_t)(((mbase + (lane & 15)) * ROW_PAD + (lane >> 4) * 8) * 2);
    const uint32_t b_off = (uint32_t)(((nbase + (lane & 7)) * ROW_PAD + ((lane >> 3) & 1) * 8) * 2);

    float acc[4][8][4];
#pragma unroll
    for (int mi = 0; mi < 4; mi++)
#pragma unroll
        for (int ni = 0; ni < 8; ni++)
#pragma unroll
            for (int r = 0; r < 4; r++) acc[mi][ni][r] = 0.f;

    auto load_stage = [&](int st, int kc) {
        const uint32_t sb = sbase + (uint32_t)st * STAGE_BYTES;
        const int k0 = kc * KC;
#pragma unroll
        for (int i = 0; i < 2; i++) {       // A hi (+ lo)
            const int idx = tid + (i << 8);
            const int r  = idx >> 2;
            const int c4 = idx & 3;
            const uint32_t soff = (uint32_t)(r * 80 + c4 * 16);
            const long long ga = (long long)(row0 + r) * Kd + k0 + c4 * 8;
            cp16(sb + soff, Ah + ga);
            if (NPROD >= 2) cp16(sb + OFF_AL + soff, Al + ga);
        }
#pragma unroll
        for (int i = 0; i < 4; i++) {       // B hi (+ lo)
            const int idx = tid + (i << 8);
            const int r  = idx >> 2;
            const int c4 = idx & 3;
            const uint32_t soff = (uint32_t)(r * 80 + c4 * 16);
            const long long gb = (long long)(col0 + r) * Kd + k0 + c4 * 8;
            cp16(sb + OFF_BH + soff, Bh + gb);
            if (NPROD == 3) cp16(sb + OFF_BL + soff, Bl + gb);
        }
        asm volatile("cp.async.commit_group;" ::: "memory");
    };

    auto compute_stage = [&](int st) {
        const uint32_t sb  = sbase + (uint32_t)st * STAGE_BYTES;
        const uint32_t aoh = sb + a_off;
        const uint32_t aol = aoh + OFF_AL;
        const uint32_t boh = sb + OFF_BH + b_off;
        const uint32_t bol = boh + B_TILE_BYTES;
#pragma unroll
        for (int kk = 0; kk < 2; kk++) {
            uint32_t ahf[4][4], bhf[8][2];
            // hh sweep
#pragma unroll
            for (int mi = 0; mi < 4; mi++) ldm_x4(ahf[mi], aoh + mi * 1280 + kk * 32);
#pragma unroll
            for (int ni = 0; ni < 8; ni++) ldm_x2(bhf[ni], boh + ni * 640 + kk * 32);
#pragma unroll
            for (int mi = 0; mi < 4; mi++)
#pragma unroll
                for (int ni = 0; ni < 8; ni++) mma16816(acc[mi][ni], ahf[mi], bhf[ni]);
            // lh sweep (A_lo x B_hi)
            if (NPROD >= 2) {
                uint32_t alf[4][4];
#pragma unroll
                for (int mi = 0; mi < 4; mi++) ldm_x4(alf[mi], aol + mi * 1280 + kk * 32);
#pragma unroll
                for (int mi = 0; mi < 4; mi++)
#pragma unroll
                    for (int ni = 0; ni < 8; ni++) mma16816(acc[mi][ni], alf[mi], bhf[ni]);
            }
            // hl sweep (A_hi x B_lo)
            if (NPROD == 3) {
                uint32_t blf[8][2];
#pragma unroll
                for (int ni = 0; ni < 8; ni++) ldm_x2(blf[ni], bol + ni * 640 + kk * 32);
#pragma unroll
                for (int mi = 0; mi < 4; mi++)
#pragma unroll
                    for (int ni = 0; ni < 8; ni++) mma16816(acc[mi][ni], ahf[mi], blf[ni]);
            }
        }
    };

    const int nc = Kd / KC;
    load_stage(0, 0);
    load_stage(1, 1);

    for (int c = 0; c < nc; c++) {
        if (c + 2 < nc) asm volatile("cp.async.wait_group 1;" ::: "memory");
        else            asm volatile("cp.async.wait_group 0;" ::: "memory");
        __syncthreads();
        compute_stage(c % N_STAGES);
        if (c + 2 < nc) load_stage((c + 2) % N_STAGES, c + 2);
    }

    // ---- epilogue ----
#pragma unroll
    for (int mi = 0; mi < 4; mi++) {
        const long long r = row0 + mbase + mi * 16 + g;
#pragma unroll
        for (int ni = 0; ni < 8; ni++) {
            const int cc = col0 + nbase + ni * 8 + t * 2;
            float2 v0, v1;
            v0.x = acc[mi][ni][0]; v0.y = acc[mi][ni][1];
            v1.x = acc[mi][ni][2]; v1.y = acc[mi][ni][3];
            if (BIAS) {
                const float2 bv = *(const float2*)(bias + cc);
                v0.x += bv.x; v0.y += bv.y;
                v1.x += bv.x; v1.y += bv.y;
            }
            if (RELU) {
                v0.x = fmaxf(v0.x, 0.f); v0.y = fmaxf(v0.y, 0.f);
                v1.x = fmaxf(v1.x, 0.f); v1.y = fmaxf(v1.y, 0.f);
            }
            if (OM == 0) {
                float* Cz = C + z * sC;
                *(float2*)(Cz + r * Nn + cc)       = v0;
                *(float2*)(Cz + (r + 8) * Nn + cc) = v1;
            } else {
                __half* Chz = Ch + z * sC;
                __half* Clz = Cl + z * sC;
                __half h0, h1, l0, l1;
                split1(v0.x, h0, l0); split1(v0.y, h1, l1);
                *(uint32_t*)(Chz + r * Nn + cc) = pack2(h0, h1);
                *(uint32_t*)(Clz + r * Nn + cc) = pack2(l0, l1);
                split1(v1.x, h0, l0); split1(v1.y, h1, l1);
                *(uint32_t*)(Chz + (r + 8) * Nn + cc) = pack2(h0, h1);
                *(uint32_t*)(Clz + (r + 8) * Nn + cc) = pack2(l0, l1);
            }
        }
    }
}

// ---------------------------------------------------------------------------
// fp32 -> fp16 hi/lo elementwise split
// ---------------------------------------------------------------------------
__global__ __launch_bounds__(256)
void split_kernel(const float* __restrict__ in, __half* __restrict__ oh,
                  __half* __restrict__ ol, long long n4)
{
    long long i = (long long)blockIdx.x * blockDim.x + threadIdx.x;
    if (i >= n4) return;
    float4 v = ((const float4*)in)[i];
    __half h0, h1, h2, h3, l0, l1, l2, l3;
    split1(v.x, h0, l0); split1(v.y, h1, l1);
    split1(v.z, h2, l2); split1(v.w, h3, l3);
    uint2 hv, lv;
    hv.x = pack2(h0, h1); hv.y = pack2(h2, h3);
    lv.x = pack2(l0, l1); lv.y = pack2(l2, l3);
    ((uint2*)oh)[i] = hv;
    ((uint2*)ol)[i] = lv;
}

// ---------------------------------------------------------------------------
// fp32 [R,C] -> transposed fp16 hi/lo [C,R] (batched via blockIdx.z)
// ---------------------------------------------------------------------------
__global__ __launch_bounds__(256)
void tsplit_kernel(const float* __restrict__ in, __half* __restrict__ oh,
                   __half* __restrict__ ol, int R, int C)
{
    __shared__ float t[32][33];
    const long long zoff = (long long)blockIdx.z * R * C;
    in += zoff; oh += zoff; ol += zoff;
    const int tx = threadIdx.x, ty = threadIdx.y;
    const int x = blockIdx.x * 32 + tx;
    const int y0 = blockIdx.y * 32 + ty;
#pragma unroll
    for (int i = 0; i < 32; i += 8)
        t[ty + i][tx] = in[(long long)(y0 + i) * C + x];
    __syncthreads();
    const int ox = blockIdx.y * 32 + tx;
    const int oy0 = blockIdx.x * 32 + ty;
#pragma unroll
    for (int i = 0; i < 32; i += 8) {
        float v = t[tx][ty + i];
        __half h, l;
        split1(v, h, l);
        oh[(long long)(oy0 + i) * R + ox] = h;
        ol[(long long)(oy0 + i) * R + ox] = l;
    }
}

// ---------------------------------------------------------------------------
// warp-per-row matvec: out[r] = sum_c Mrow[r,:]*v[:]   (C = D_EMB)
// ---------------------------------------------------------------------------
__inline__ __device__ float warpSum(float v) {
#pragma unroll
    for (int o = 16; o > 0; o >>= 1) v += __shfl_xor_sync(0xffffffffu, v, o);
    return v;
}
__inline__ __device__ float warpMax(float v) {
#pragma unroll
    for (int o = 16; o > 0; o >>= 1) v = fmaxf(v, __shfl_xor_sync(0xffffffffu, v, o));
    return v;
}

__global__ __launch_bounds__(256)
void matvec_kernel(const float* __restrict__ Mrow, const float* __restrict__ v,
                   float* __restrict__ out)
{
    const int row  = blockIdx.x * 8 + (threadIdx.x >> 5);
    const int lane = threadIdx.x & 31;
    const float* R = Mrow + (long long)row * D_EMB;
    float s = 0.f;
#pragma unroll
    for (int d = lane * 4; d < D_EMB; d += 128) {
        const float4 a = *(const float4*)(R + d);
        const float4 b = *(const float4*)(v + d);
        s += a.x * b.x + a.y * b.y + a.z * b.z + a.w * b.w;
    }
    s = warpSum(s);
    if (lane == 0) out[row] = s;
}

// ---------------------------------------------------------------------------
// Row softmax over 2048 fp32 (+ per-i offset w) -> fp16 hi output only
// ---------------------------------------------------------------------------
__global__ __launch_bounds__(256)
void softmax_split(const float* __restrict__ S, const float* __restrict__ w,
                   __half* __restrict__ ah)
{
    const long long base = (long long)blockIdx.x * N_SEQ;
    const float* row = S + base;
    const float* wb  = w + (long long)(blockIdx.x >> 11) * N_SEQ;  // batch = blk / 2048
    const int tid = threadIdx.x;
    const int lane = tid & 31;
    const int wid = tid >> 5;

    float4 v0 = ((const float4*)row)[tid];
    float4 v1 = ((const float4*)row)[tid + 256];
    const float4 w0 = ((const float4*)wb)[tid];
    const float4 w1 = ((const float4*)wb)[tid + 256];
    v0.x += w0.x; v0.y += w0.y; v0.z += w0.z; v0.w += w0.w;
    v1.x += w1.x; v1.y += w1.y; v1.z += w1.z; v1.w += w1.w;

    __shared__ float sm[8];
    float m = fmaxf(fmaxf(fmaxf(v0.x, v0.y), fmaxf(v0.z, v0.w)),
                    fmaxf(fmaxf(v1.x, v1.y), fmaxf(v1.z, v1.w)));
    m = warpMax(m);
    if (lane == 0) sm[wid] = m;
    __syncthreads();
    if (wid == 0) {
        float t = (lane < 8) ? sm[lane] : -3.402823e38f;
        t = warpMax(t);
        if (lane == 0) sm[0] = t;
    }
    __syncthreads();
    m = sm[0];
    __syncthreads();

    v0.x = expf(v0.x - m); v0.y = expf(v0.y - m);
    v0.z = expf(v0.z - m); v0.w = expf(v0.w - m);
    v1.x = expf(v1.x - m); v1.y = expf(v1.y - m);
    v1.z = expf(v1.z - m); v1.w = expf(v1.w - m);

    float s = (v0.x + v0.y + v0.z + v0.w) + (v1.x + v1.y + v1.z + v1.w);
    s = warpSum(s);
    if (lane == 0) sm[wid] = s;
    __syncthreads();
    if (wid == 0) {
        float t = (lane < 8) ? sm[lane] : 0.f;
        t = warpSum(t);
        if (lane == 0) sm[0] = t;
    }
    __syncthreads();
    const float inv = 1.0f / sm[0];

    uint2 hv;
    hv.x = pack2(__float2half(v0.x * inv), __float2half(v0.y * inv));
    hv.y = pack2(__float2half(v0.z * inv), __float2half(v0.w * inv));
    ((uint2*)(ah + base))[tid] = hv;
    hv.x = pack2(__float2half(v1.x * inv), __float2half(v1.y * inv));
    hv.y = pack2(__float2half(v1.z * inv), __float2half(v1.w * inv));
    ((uint2*)(ah + base))[tid + 256] = hv;
}

// ---------------------------------------------------------------------------
extern "C" void kernel_launch(void* const* d_in, const int* in_sizes, int n_in,
                              void* d_out, int out_size)
{
    const float* x  = (const float*)d_in[0];
    const float* Wq = (const float*)d_in[1];
    const float* bq = (const float*)d_in[2];
    const float* Wk = (const float*)d_in[3];
    const float* bk = (const float*)d_in[4];
    const float* Wv = (const float*)d_in[5];
    const float* bv = (const float*)d_in[6];
    const float* Wm = (const float*)d_in[7];
    const float* bm = (const float*)d_in[8];
    float* out = (float*)d_out;
    (void)bq;  // bq enters scores only via terms constant along the softmax axis

    __half *xh, *xl, *Wqh, *Wql, *Wkh, *Wkl, *Wvh, *Wvl, *Wmh, *Wml;
    __half *M2h, *M2l, *Zh, *Zl, *Vth, *Vtl, *Th, *Tl, *ah;
    float *Vf, *S, *wv, *w;
    cudaGetSymbolAddress((void**)&xh, g_xh);   cudaGetSymbolAddress((void**)&xl, g_xl);
    cudaGetSymbolAddress((void**)&Wqh, g_Wqh); cudaGetSymbolAddress((void**)&Wql, g_Wql);
    cudaGetSymbolAddress((void**)&Wkh, g_Wkh); cudaGetSymbolAddress((void**)&Wkl, g_Wkl);
    cudaGetSymbolAddress((void**)&Wvh, g_Wvh); cudaGetSymbolAddress((void**)&Wvl, g_Wvl);
    cudaGetSymbolAddress((void**)&Wmh, g_Wmh); cudaGetSymbolAddress((void**)&Wml, g_Wml);
    cudaGetSymbolAddress((void**)&M2h, g_M2h); cudaGetSymbolAddress((void**)&M2l, g_M2l);
    cudaGetSymbolAddress((void**)&Zh, g_Zh);   cudaGetSymbolAddress((void**)&Zl, g_Zl);
    cudaGetSymbolAddress((void**)&Vf, g_Vf);
    cudaGetSymbolAddress((void**)&Vth, g_Vth); cudaGetSymbolAddress((void**)&Vtl, g_Vtl);
    cudaGetSymbolAddress((void**)&Th, g_Th);   cudaGetSymbolAddress((void**)&Tl, g_Tl);
    cudaGetSymbolAddress((void**)&ah, g_ah);
    cudaGetSymbolAddress((void**)&S, g_S);
    cudaGetSymbolAddress((void**)&wv, g_wv);   cudaGetSymbolAddress((void**)&w, g_w);

    cudaFuncSetAttribute(gemm_mma<3, 1, false, false>,
                         cudaFuncAttributeMaxDynamicSharedMemorySize, SMEM_BYTES);
    cudaFuncSetAttribute(gemm_mma<3, 0, false, false>,
                         cudaFuncAttributeMaxDynamicSharedMemorySize, SMEM_BYTES);
    cudaFuncSetAttribute(gemm_mma<2, 0, true, false>,
                         cudaFuncAttributeMaxDynamicSharedMemorySize, SMEM_BYTES);
    cudaFuncSetAttribute(gemm_mma<1, 1, false, false>,
                         cudaFuncAttributeMaxDynamicSharedMemorySize, SMEM_BYTES);
    cudaFuncSetAttribute(gemm_mma<2, 0, true, true>,
                         cudaFuncAttributeMaxDynamicSharedMemorySize, SMEM_BYTES);

    const long long nX = (long long)BN_TOT * D_EMB;
    const long long nW = (long long)D_EMB * D_EMB;

    // 1) split x (plain); split Wq, Wk (plain, K-contiguous rows)
    split_kernel<<<(unsigned)((nX / 4 + 255) / 256), 256>>>(x, xh, xl, nX / 4);
    split_kernel<<<(unsigned)((nW / 4 + 255) / 256), 256>>>(Wq, Wqh, Wql, nW / 4);
    split_kernel<<<(unsigned)((nW / 4 + 255) / 256), 256>>>(Wk, Wkh, Wkl, nW / 4);

    // 2) transpose-split Wv, Wm (used as [n,k] B operands)
    {
        dim3 g(D_EMB / 32, D_EMB / 32, 1), b(32, 8);
        tsplit_kernel<<<g, b>>>(Wv, Wvh, Wvl, D_EMB, D_EMB);
        tsplit_kernel<<<g, b>>>(Wm, Wmh, Wml, D_EMB, D_EMB);
    }

    // 3) M2[f,e] = sum_d Wq[f,d]*Wk[e,d], 3-MMA, split epilogue
    {
        dim3 g(D_EMB / 256, D_EMB / 128, 1);
        gemm_mma<3, 1, false, false><<<g, 256, SMEM_BYTES>>>(
            Wqh, Wql, Wkh, Wkl, nullptr, nullptr, M2h, M2l, D_EMB, D_EMB, 0, 0, 0);
    }

    // 4) bias correction vector: wv = Wq*bk ; w = x*wv  (exact rank-1 term)
    matvec_kernel<<<D_EMB / 8, 256>>>(Wq, bk, wv);
    matvec_kernel<<<BN_TOT / 8, 256>>>(x, wv, w);

    // 5) V projection (2-MMA): V = x @ Wv + bv (fp32), then transpose-split
    {
        dim3 g(D_EMB / 256, BN_TOT / 128, 1);
        gemm_mma<2, 0, true, false><<<g, 256, SMEM_BYTES>>>(
            xh, xl, Wvh, nullptr, bv, Vf, nullptr, nullptr, D_EMB, D_EMB, 0, 0, 0);
        dim3 gt(D_EMB / 32, N_SEQ / 32, N_BATCH), bt(32, 8);
        tsplit_kernel<<<gt, bt>>>(Vf, Vth, Vtl, N_SEQ, D_EMB);
    }

    // 6) Z = x @ M  (3-MMA, split epilogue)
    {
        dim3 g(D_EMB / 256, BN_TOT / 128, 1);
        gemm_mma<3, 1, false, false><<<g, 256, SMEM_BYTES>>>(
            xh, xl, M2h, M2l, nullptr, nullptr, Zh, Zl, D_EMB, D_EMB, 0, 0, 0);
    }

    // 7) S'[b,j,i] = Z_b[j,:] . x_b[i,:]  (3-MMA, M=N=2048, K=1024, batched)
    {
        dim3 g(N_SEQ / 256, N_SEQ / 128, N_BATCH);
        gemm_mma<3, 0, false, false><<<g, 256, SMEM_BYTES>>>(
            Zh, Zl, xh, xl, nullptr, S, nullptr, nullptr, N_SEQ, D_EMB,
            (long long)N_SEQ * D_EMB, (long long)N_SEQ * D_EMB,
            (long long)N_SEQ * N_SEQ);
    }

    // 8) row softmax (with +w_i offset) -> alpha hi only
    softmax_split<<<BN_TOT, 256>>>(S, w, ah);

    // 9) T[b] = alpha_b @ V_b via Vt (1-MMA: alpha_hi x V_hi), split epilogue
    {
        dim3 g(D_EMB / 256, N_SEQ / 128, N_BATCH);
        gemm_mma<1, 1, false, false><<<g, 256, SMEM_BYTES>>>(
            ah, nullptr, Vth, nullptr, nullptr, nullptr, Th, Tl, D_EMB, N_SEQ,
            (long long)N_SEQ * N_SEQ, (long long)D_EMB * N_SEQ,
            (long long)N_SEQ * D_EMB);
    }

    // 10) out = relu(T @ Wm + bm)  (2-MMA, B = Wmh only)
    {
        dim3 g(D_EMB / 256, BN_TOT / 128, 1);
        gemm_mma<2, 0, true, true><<<g, 256, SMEM_BYTES>>>(
            Th, Tl, Wmh, nullptr, bm, out, nullptr, nullptr, D_EMB, D_EMB, 0, 0, 0);
    }
}

// round 10
// speedup vs baseline: 4.4787x; 1.2279x over previous
#include <cuda_runtime.h>
#include <cuda_fp16.h>
#include <stdint.h>
#include <math.h>

#define D_EMB   1024
#define N_BATCH 4
#define N_SEQ   2048
#define BN_TOT  (N_BATCH * N_SEQ)   // 8192

// ---------------------------------------------------------------------------
// Device scratch (allocation-free per harness rules)
// ---------------------------------------------------------------------------
__device__ __half g_xh[BN_TOT * D_EMB], g_xl[BN_TOT * D_EMB];
__device__ __half g_Wqh[D_EMB * D_EMB], g_Wql[D_EMB * D_EMB];  // plain split
__device__ __half g_Wkh[D_EMB * D_EMB], g_Wkl[D_EMB * D_EMB];  // plain split
__device__ __half g_Wvh[D_EMB * D_EMB], g_Wvl[D_EMB * D_EMB];  // transposed split
__device__ __half g_Wmh[D_EMB * D_EMB], g_Wml[D_EMB * D_EMB];  // transposed split
__device__ __half g_M2h[D_EMB * D_EMB], g_M2l[D_EMB * D_EMB];  // Wq*Wk^T
__device__ __half g_Zh[BN_TOT * D_EMB], g_Zl[BN_TOT * D_EMB];  // x*M
__device__ float g_Vf[BN_TOT * D_EMB];
__device__ __half g_Vth[BN_TOT * D_EMB], g_Vtl[BN_TOT * D_EMB];
__device__ __half g_Th[BN_TOT * D_EMB];
__device__ float g_S[(size_t)N_BATCH * N_SEQ * N_SEQ];
__device__ __half g_ah[(size_t)N_BATCH * N_SEQ * N_SEQ];   // alpha hi only
__device__ float g_wv[D_EMB];     // Wq * bk
__device__ float g_w[BN_TOT];     // x * (Wq*bk)  -- per-query softmax offset

// ---------------------------------------------------------------------------
// static streams/events for graph-capture fork/join (created at load time;
// no device memory involved)
// ---------------------------------------------------------------------------
static cudaStream_t g_sB;
static cudaEvent_t g_e0, g_eX, g_eW, g_eV;
static struct StreamInit {
    StreamInit() {
        cudaStreamCreateWithFlags(&g_sB, cudaStreamNonBlocking);
        cudaEventCreateWithFlags(&g_e0, cudaEventDisableTiming);
        cudaEventCreateWithFlags(&g_eX, cudaEventDisableTiming);
        cudaEventCreateWithFlags(&g_eW, cudaEventDisableTiming);
        cudaEventCreateWithFlags(&g_eV, cudaEventDisableTiming);
    }
} g_stream_init;

// ---------------------------------------------------------------------------
// helpers
// ---------------------------------------------------------------------------
__device__ __forceinline__ uint32_t smem_u32(const void* p) {
    uint32_t a;
    asm("{ .reg .u64 t; cvta.to.shared.u64 t, %1; cvt.u32.u64 %0, t; }"
        : "=r"(a) : "l"(p));
    return a;
}
__device__ __forceinline__ uint64_t gptr64(const void* p) {
    uint64_t g;
    asm("cvta.to.global.u64 %0, %1;" : "=l"(g) : "l"(p));
    return g;
}
__device__ __forceinline__ void cp16(uint32_t saddr, const void* g) {
    asm volatile("cp.async.cg.shared.global [%0], [%1], 16;"
                 :: "r"(saddr), "l"(gptr64(g)) : "memory");
}

// warp-level fp16 MMA, fp32 accumulate (fallback HMMA on sm_103)
__device__ __forceinline__ void mma16816(float* c, const uint32_t* a, const uint32_t* b) {
    asm volatile(
        "mma.sync.aligned.m16n8k16.row.col.f32.f16.f16.f32 "
        "{%0,%1,%2,%3}, {%4,%5,%6,%7}, {%8,%9}, {%0,%1,%2,%3};"
        : "+f"(c[0]), "+f"(c[1]), "+f"(c[2]), "+f"(c[3])
        : "r"(a[0]), "r"(a[1]), "r"(a[2]), "r"(a[3]), "r"(b[0]), "r"(b[1]));
}
__device__ __forceinline__ void ldm_x4(uint32_t* r, uint32_t addr) {
    asm volatile("ldmatrix.sync.aligned.m8n8.x4.shared.b16 {%0,%1,%2,%3}, [%4];"
                 : "=r"(r[0]), "=r"(r[1]), "=r"(r[2]), "=r"(r[3]) : "r"(addr));
}
// NON-transposed x2: correct for B stored [N,K] row-major (K-contiguous)
__device__ __forceinline__ void ldm_x2(uint32_t* r, uint32_t addr) {
    asm volatile("ldmatrix.sync.aligned.m8n8.x2.shared.b16 {%0,%1}, [%2];"
                 : "=r"(r[0]), "=r"(r[1]) : "r"(addr));
}

__device__ __forceinline__ void split1(float v, __half& h, __half& l) {
    h = __float2half(v);
    l = __float2half(v - __half2float(h));
}
__device__ __forceinline__ uint32_t pack2(__half a, __half b) {
    __half2 t; t.x = a; t.y = b;
    return *reinterpret_cast<uint32_t*>(&t);
}

// smem geometry: rows padded to 40 fp16 (80B) -> conflict-free ldmatrix
#define KC          32
#define ROW_PAD     40
#define A_TILE_BYTES (128 * ROW_PAD * 2)         // 10240
#define B_TILE_BYTES (256 * ROW_PAD * 2)         // 20480
// stage layout: Ah | Al | Bh | Bl
#define OFF_AL      A_TILE_BYTES                 // 10240
#define OFF_BH      (2 * A_TILE_BYTES)           // 20480
#define OFF_BL      (2 * A_TILE_BYTES + B_TILE_BYTES)  // 40960
#define STAGE_BYTES (2 * A_TILE_BYTES + 2 * B_TILE_BYTES)  // 61440
#define N_STAGES    3
#define SMEM_BYTES  (N_STAGES * STAGE_BYTES)     // 184320

// ---------------------------------------------------------------------------
// NT GEMM: C = (Ah+Al)[M,K] @ (Bh+Bl)[N,K]^T, fp16 split.
// NPROD=3: hh+lh+hl. NPROD=2: hh+lh (no B_lo). NPROD=1: hh only.
// CTA 128x256, 8 warps (2x4), warp tile 64x64, 3-stage cp.async pipeline.
// OM=0: fp32 C. OM=1: fp16 hi/lo split (Ch, Cl). OM=2: fp16 hi only (Ch).
// M mult of 128, N mult of 256, K mult of 32.
// ---------------------------------------------------------------------------
template <int NPROD, int OM, bool BIAS, bool RELU>
__global__ __launch_bounds__(256, 1)
void gemm_mma(const __half* __restrict__ Ah, const __half* __restrict__ Al,
              const __half* __restrict__ Bh, const __half* __restrict__ Bl,
              const float* __restrict__ bias, float* __restrict__ C,
              __half* __restrict__ Ch, __half* __restrict__ Cl,
              int Nn, int Kd, long long sA, long long sB, long long sC)
{
    extern __shared__ __align__(128) char smem[];
    const int tid = threadIdx.x;
    const long long z = blockIdx.z;
    Ah += z * sA;
    if (NPROD >= 2) Al += z * sA;
    Bh += z * sB;
    if (NPROD == 3) Bl += z * sB;
    const int row0 = blockIdx.y * 128;
    const int col0 = blockIdx.x * 256;

    const int warp  = tid >> 5;
    const int lane  = tid & 31;
    const int g     = lane >> 2;
    const int t     = lane & 3;
    const int mbase = (warp & 1) * 64;
    const int nbase = (warp >> 1) * 64;

    const uint32_t sbase = smem_u32(smem);

    const uint32_t a_off = (uint32_t)(((mbase + (lane & 15)) * ROW_PAD + (lane >> 4) * 8) * 2);
    const uint32_t b_off = (uint32_t)(((nbase + (lane & 7)) * ROW_PAD + ((lane >> 3) & 1) * 8) * 2);

    float acc[4][8][4];
#pragma unroll
    for (int mi = 0; mi < 4; mi++)
#pragma unroll
        for (int ni = 0; ni < 8; ni++)
#pragma unroll
            for (int r = 0; r < 4; r++) acc[mi][ni][r] = 0.f;

    auto load_stage = [&](int st, int kc) {
        const uint32_t sb = sbase + (uint32_t)st * STAGE_BYTES;
        const int k0 = kc * KC;
#pragma unroll
        for (int i = 0; i < 2; i++) {       // A hi (+ lo)
            const int idx = tid + (i << 8);
            const int r  = idx >> 2;
            const int c4 = idx & 3;
            const uint32_t soff = (uint32_t)(r * 80 + c4 * 16);
            const long long ga = (long long)(row0 + r) * Kd + k0 + c4 * 8;
            cp16(sb + soff, Ah + ga);
            if (NPROD >= 2) cp16(sb + OFF_AL + soff, Al + ga);
        }
#pragma unroll
        for (int i = 0; i < 4; i++) {       // B hi (+ lo)
            const int idx = tid + (i << 8);
            const int r  = idx >> 2;
            const int c4 = idx & 3;
            const uint32_t soff = (uint32_t)(r * 80 + c4 * 16);
            const long long gb = (long long)(col0 + r) * Kd + k0 + c4 * 8;
            cp16(sb + OFF_BH + soff, Bh + gb);
            if (NPROD == 3) cp16(sb + OFF_BL + soff, Bl + gb);
        }
        asm volatile("cp.async.commit_group;" ::: "memory");
    };

    auto compute_stage = [&](int st) {
        const uint32_t sb  = sbase + (uint32_t)st * STAGE_BYTES;
        const uint32_t aoh = sb + a_off;
        const uint32_t aol = aoh + OFF_AL;
        const uint32_t boh = sb + OFF_BH + b_off;
        const uint32_t bol = boh + B_TILE_BYTES;
#pragma unroll
        for (int kk = 0; kk < 2; kk++) {
            uint32_t ahf[4][4], bhf[8][2];
            // hh sweep
#pragma unroll
            for (int mi = 0; mi < 4; mi++) ldm_x4(ahf[mi], aoh + mi * 1280 + kk * 32);
#pragma unroll
            for (int ni = 0; ni < 8; ni++) ldm_x2(bhf[ni], boh + ni * 640 + kk * 32);
#pragma unroll
            for (int mi = 0; mi < 4; mi++)
#pragma unroll
                for (int ni = 0; ni < 8; ni++) mma16816(acc[mi][ni], ahf[mi], bhf[ni]);
            // lh sweep (A_lo x B_hi)
            if (NPROD >= 2) {
                uint32_t alf[4][4];
#pragma unroll
                for (int mi = 0; mi < 4; mi++) ldm_x4(alf[mi], aol + mi * 1280 + kk * 32);
#pragma unroll
                for (int mi = 0; mi < 4; mi++)
#pragma unroll
                    for (int ni = 0; ni < 8; ni++) mma16816(acc[mi][ni], alf[mi], bhf[ni]);
            }
            // hl sweep (A_hi x B_lo)
            if (NPROD == 3) {
                uint32_t blf[8][2];
#pragma unroll
                for (int ni = 0; ni < 8; ni++) ldm_x2(blf[ni], bol + ni * 640 + kk * 32);
#pragma unroll
                for (int mi = 0; mi < 4; mi++)
#pragma unroll
                    for (int ni = 0; ni < 8; ni++) mma16816(acc[mi][ni], ahf[mi], blf[ni]);
            }
        }
    };

    const int nc = Kd / KC;
    load_stage(0, 0);
    load_stage(1, 1);

    for (int c = 0; c < nc; c++) {
        if (c + 2 < nc) asm volatile("cp.async.wait_group 1;" ::: "memory");
        else            asm volatile("cp.async.wait_group 0;" ::: "memory");
        __syncthreads();
        compute_stage(c % N_STAGES);
        if (c + 2 < nc) load_stage((c + 2) % N_STAGES, c + 2);
    }

    // ---- epilogue ----
#pragma unroll
    for (int mi = 0; mi < 4; mi++) {
        const long long r = row0 + mbase + mi * 16 + g;
#pragma unroll
        for (int ni = 0; ni < 8; ni++) {
            const int cc = col0 + nbase + ni * 8 + t * 2;
            float2 v0, v1;
            v0.x = acc[mi][ni][0]; v0.y = acc[mi][ni][1];
            v1.x = acc[mi][ni][2]; v1.y = acc[mi][ni][3];
            if (BIAS) {
                const float2 bv = *(const float2*)(bias + cc);
                v0.x += bv.x; v0.y += bv.y;
                v1.x += bv.x; v1.y += bv.y;
            }
            if (RELU) {
                v0.x = fmaxf(v0.x, 0.f); v0.y = fmaxf(v0.y, 0.f);
                v1.x = fmaxf(v1.x, 0.f); v1.y = fmaxf(v1.y, 0.f);
            }
            if (OM == 0) {
                float* Cz = C + z * sC;
                *(float2*)(Cz + r * Nn + cc)       = v0;
                *(float2*)(Cz + (r + 8) * Nn + cc) = v1;
            } else if (OM == 1) {
                __half* Chz = Ch + z * sC;
                __half* Clz = Cl + z * sC;
                __half h0, h1, l0, l1;
                split1(v0.x, h0, l0); split1(v0.y, h1, l1);
                *(uint32_t*)(Chz + r * Nn + cc) = pack2(h0, h1);
                *(uint32_t*)(Clz + r * Nn + cc) = pack2(l0, l1);
                split1(v1.x, h0, l0); split1(v1.y, h1, l1);
                *(uint32_t*)(Chz + (r + 8) * Nn + cc) = pack2(h0, h1);
                *(uint32_t*)(Clz + (r + 8) * Nn + cc) = pack2(l0, l1);
            } else {
                __half* Chz = Ch + z * sC;
                *(uint32_t*)(Chz + r * Nn + cc) =
                    pack2(__float2half(v0.x), __float2half(v0.y));
                *(uint32_t*)(Chz + (r + 8) * Nn + cc) =
                    pack2(__float2half(v1.x), __float2half(v1.y));
            }
        }
    }
}

// ---------------------------------------------------------------------------
// fp32 -> fp16 hi/lo elementwise split
// ---------------------------------------------------------------------------
__global__ __launch_bounds__(256)
void split_kernel(const float* __restrict__ in, __half* __restrict__ oh,
                  __half* __restrict__ ol, long long n4)
{
    long long i = (long long)blockIdx.x * blockDim.x + threadIdx.x;
    if (i >= n4) return;
    float4 v = ((const float4*)in)[i];
    __half h0, h1, h2, h3, l0, l1, l2, l3;
    split1(v.x, h0, l0); split1(v.y, h1, l1);
    split1(v.z, h2, l2); split1(v.w, h3, l3);
    uint2 hv, lv;
    hv.x = pack2(h0, h1); hv.y = pack2(h2, h3);
    lv.x = pack2(l0, l1); lv.y = pack2(l2, l3);
    ((uint2*)oh)[i] = hv;
    ((uint2*)ol)[i] = lv;
}

// ---------------------------------------------------------------------------
// fp32 [R,C] -> transposed fp16 hi/lo [C,R] (batched via blockIdx.z)
// ---------------------------------------------------------------------------
__global__ __launch_bounds__(256)
void tsplit_kernel(const float* __restrict__ in, __half* __restrict__ oh,
                   __half* __restrict__ ol, int R, int C)
{
    __shared__ float t[32][33];
    const long long zoff = (long long)blockIdx.z * R * C;
    in += zoff; oh += zoff; ol += zoff;
    const int tx = threadIdx.x, ty = threadIdx.y;
    const int x = blockIdx.x * 32 + tx;
    const int y0 = blockIdx.y * 32 + ty;
#pragma unroll
    for (int i = 0; i < 32; i += 8)
        t[ty + i][tx] = in[(long long)(y0 + i) * C + x];
    __syncthreads();
    const int ox = blockIdx.y * 32 + tx;
    const int oy0 = blockIdx.x * 32 + ty;
#pragma unroll
    for (int i = 0; i < 32; i += 8) {
        float v = t[tx][ty + i];
        __half h, l;
        split1(v, h, l);
        oh[(long long)(oy0 + i) * R + ox] = h;
        ol[(long long)(oy0 + i) * R + ox] = l;
    }
}

// ---------------------------------------------------------------------------
// warp-per-row matvec: out[r] = sum_c Mrow[r,:]*v[:]   (C = D_EMB)
// ---------------------------------------------------------------------------
__inline__ __device__ float warpSum(float v) {
#pragma unroll
    for (int o = 16; o > 0; o >>= 1) v += __shfl_xor_sync(0xffffffffu, v, o);
    return v;
}
__inline__ __device__ float warpMax(float v) {
#pragma unroll
    for (int o = 16; o > 0; o >>= 1) v = fmaxf(v, __shfl_xor_sync(0xffffffffu, v, o));
    return v;
}

__global__ __launch_bounds__(256)
void matvec_kernel(const float* __restrict__ Mrow, const float* __restrict__ v,
                   float* __restrict__ out)
{
    const int row  = blockIdx.x * 8 + (threadIdx.x >> 5);
    const int lane = threadIdx.x & 31;
    const float* R = Mrow + (long long)row * D_EMB;
    float s = 0.f;
#pragma unroll
    for (int d = lane * 4; d < D_EMB; d += 128) {
        const float4 a = *(const float4*)(R + d);
        const float4 b = *(const float4*)(v + d);
        s += a.x * b.x + a.y * b.y + a.z * b.z + a.w * b.w;
    }
    s = warpSum(s);
    if (lane == 0) out[row] = s;
}

// ---------------------------------------------------------------------------
// Row softmax over 2048 fp32 (+ per-i offset w) -> fp16 hi output only
// ---------------------------------------------------------------------------
__global__ __launch_bounds__(256)
void softmax_split(const float* __restrict__ S, const float* __restrict__ w,
                   __half* __restrict__ ah)
{
    const long long base = (long long)blockIdx.x * N_SEQ;
    const float* row = S + base;
    const float* wb  = w + (long long)(blockIdx.x >> 11) * N_SEQ;  // batch = blk / 2048
    const int tid = threadIdx.x;
    const int lane = tid & 31;
    const int wid = tid >> 5;

    float4 v0 = ((const float4*)row)[tid];
    float4 v1 = ((const float4*)row)[tid + 256];
    const float4 w0 = ((const float4*)wb)[tid];
    const float4 w1 = ((const float4*)wb)[tid + 256];
    v0.x += w0.x; v0.y += w0.y; v0.z += w0.z; v0.w += w0.w;
    v1.x += w1.x; v1.y += w1.y; v1.z += w1.z; v1.w += w1.w;

    __shared__ float sm[8];
    float m = fmaxf(fmaxf(fmaxf(v0.x, v0.y), fmaxf(v0.z, v0.w)),
                    fmaxf(fmaxf(v1.x, v1.y), fmaxf(v1.z, v1.w)));
    m = warpMax(m);
    if (lane == 0) sm[wid] = m;
    __syncthreads();
    if (wid == 0) {
        float t = (lane < 8) ? sm[lane] : -3.402823e38f;
        t = warpMax(t);
        if (lane == 0) sm[0] = t;
    }
    __syncthreads();
    m = sm[0];
    __syncthreads();

    v0.x = expf(v0.x - m); v0.y = expf(v0.y - m);
    v0.z = expf(v0.z - m); v0.w = expf(v0.w - m);
    v1.x = expf(v1.x - m); v1.y = expf(v1.y - m);
    v1.z = expf(v1.z - m); v1.w = expf(v1.w - m);

    float s = (v0.x + v0.y + v0.z + v0.w) + (v1.x + v1.y + v1.z + v1.w);
    s = warpSum(s);
    if (lane == 0) sm[wid] = s;
    __syncthreads();
    if (wid == 0) {
        float t = (lane < 8) ? sm[lane] : 0.f;
        t = warpSum(t);
        if (lane == 0) sm[0] = t;
    }
    __syncthreads();
    const float inv = 1.0f / sm[0];

    uint2 hv;
    hv.x = pack2(__float2half(v0.x * inv), __float2half(v0.y * inv));
    hv.y = pack2(__float2half(v0.z * inv), __float2half(v0.w * inv));
    ((uint2*)(ah + base))[tid] = hv;
    hv.x = pack2(__float2half(v1.x * inv), __float2half(v1.y * inv));
    hv.y = pack2(__float2half(v1.z * inv), __float2half(v1.w * inv));
    ((uint2*)(ah + base))[tid + 256] = hv;
}

// ---------------------------------------------------------------------------
extern "C" void kernel_launch(void* const* d_in, const int* in_sizes, int n_in,
                              void* d_out, int out_size)
{
    const float* x  = (const float*)d_in[0];
    const float* Wq = (const float*)d_in[1];
    const float* bq = (const float*)d_in[2];
    const float* Wk = (const float*)d_in[3];
    const float* bk = (const float*)d_in[4];
    const float* Wv = (const float*)d_in[5];
    const float* bv = (const float*)d_in[6];
    const float* Wm = (const float*)d_in[7];
    const float* bm = (const float*)d_in[8];
    float* out = (float*)d_out;
    (void)bq;  // bq enters scores only via terms constant along the softmax axis

    __half *xh, *xl, *Wqh, *Wql, *Wkh, *Wkl, *Wvh, *Wvl, *Wmh, *Wml;
    __half *M2h, *M2l, *Zh, *Zl, *Vth, *Vtl, *Th, *ah;
    float *Vf, *S, *wv, *w;
    cudaGetSymbolAddress((void**)&xh, g_xh);   cudaGetSymbolAddress((void**)&xl, g_xl);
    cudaGetSymbolAddress((void**)&Wqh, g_Wqh); cudaGetSymbolAddress((void**)&Wql, g_Wql);
    cudaGetSymbolAddress((void**)&Wkh, g_Wkh); cudaGetSymbolAddress((void**)&Wkl, g_Wkl);
    cudaGetSymbolAddress((void**)&Wvh, g_Wvh); cudaGetSymbolAddress((void**)&Wvl, g_Wvl);
    cudaGetSymbolAddress((void**)&Wmh, g_Wmh); cudaGetSymbolAddress((void**)&Wml, g_Wml);
    cudaGetSymbolAddress((void**)&M2h, g_M2h); cudaGetSymbolAddress((void**)&M2l, g_M2l);
    cudaGetSymbolAddress((void**)&Zh, g_Zh);   cudaGetSymbolAddress((void**)&Zl, g_Zl);
    cudaGetSymbolAddress((void**)&Vf, g_Vf);
    cudaGetSymbolAddress((void**)&Vth, g_Vth); cudaGetSymbolAddress((void**)&Vtl, g_Vtl);
    cudaGetSymbolAddress((void**)&Th, g_Th);
    cudaGetSymbolAddress((void**)&ah, g_ah);
    cudaGetSymbolAddress((void**)&S, g_S);
    cudaGetSymbolAddress((void**)&wv, g_wv);   cudaGetSymbolAddress((void**)&w, g_w);

    cudaFuncSetAttribute(gemm_mma<3, 1, false, false>,
                         cudaFuncAttributeMaxDynamicSharedMemorySize, SMEM_BYTES);
    cudaFuncSetAttribute(gemm_mma<3, 0, false, false>,
                         cudaFuncAttributeMaxDynamicSharedMemorySize, SMEM_BYTES);
    cudaFuncSetAttribute(gemm_mma<1, 0, true, false>,
                         cudaFuncAttributeMaxDynamicSharedMemorySize, SMEM_BYTES);
    cudaFuncSetAttribute(gemm_mma<1, 2, false, false>,
                         cudaFuncAttributeMaxDynamicSharedMemorySize, SMEM_BYTES);
    cudaFuncSetAttribute(gemm_mma<1, 0, true, true>,
                         cudaFuncAttributeMaxDynamicSharedMemorySize, SMEM_BYTES);

    const long long nX = (long long)BN_TOT * D_EMB;
    const long long nW = (long long)D_EMB * D_EMB;

    // ---- fork side stream (capture-legal event fork) ----
    cudaEventRecord(g_e0, 0);
    cudaStreamWaitEvent(g_sB, g_e0, 0);

    // side stream: weight transposes + bias matvecs (independent of main chain)
    {
        dim3 g(D_EMB / 32, D_EMB / 32, 1), b(32, 8);
        tsplit_kernel<<<g, b, 0, g_sB>>>(Wv, Wvh, Wvl, D_EMB, D_EMB);
        tsplit_kernel<<<g, b, 0, g_sB>>>(Wm, Wmh, Wml, D_EMB, D_EMB);
    }
    matvec_kernel<<<D_EMB / 8, 256, 0, g_sB>>>(Wq, bk, wv);
    matvec_kernel<<<BN_TOT / 8, 256, 0, g_sB>>>(x, wv, w);
    cudaEventRecord(g_eW, g_sB);

    // main stream: split x (needed by V proj on side stream, and Z/S here)
    split_kernel<<<(unsigned)((nX / 4 + 255) / 256), 256>>>(x, xh, xl, nX / 4);
    cudaEventRecord(g_eX, 0);
    cudaStreamWaitEvent(g_sB, g_eX, 0);

    // side stream: V projection (1-MMA) + transpose-split of V
    {
        dim3 g(D_EMB / 256, BN_TOT / 128, 1);
        gemm_mma<1, 0, true, false><<<g, 256, SMEM_BYTES, g_sB>>>(
            xh, nullptr, Wvh, nullptr, bv, Vf, nullptr, nullptr, D_EMB, D_EMB, 0, 0, 0);
        dim3 gt(D_EMB / 32, N_SEQ / 32, N_BATCH), bt(32, 8);
        tsplit_kernel<<<gt, bt, 0, g_sB>>>(Vf, Vth, Vtl, N_SEQ, D_EMB);
    }
    cudaEventRecord(g_eV, g_sB);

    // main stream: Wq/Wk splits -> M2 -> Z -> S
    split_kernel<<<(unsigned)((nW / 4 + 255) / 256), 256>>>(Wq, Wqh, Wql, nW / 4);
    split_kernel<<<(unsigned)((nW / 4 + 255) / 256), 256>>>(Wk, Wkh, Wkl, nW / 4);
    {
        dim3 g(D_EMB / 256, D_EMB / 128, 1);
        gemm_mma<3, 1, false, false><<<g, 256, SMEM_BYTES>>>(
            Wqh, Wql, Wkh, Wkl, nullptr, nullptr, M2h, M2l, D_EMB, D_EMB, 0, 0, 0);
    }
    {
        dim3 g(D_EMB / 256, BN_TOT / 128, 1);
        gemm_mma<3, 1, false, false><<<g, 256, SMEM_BYTES>>>(
            xh, xl, M2h, M2l, nullptr, nullptr, Zh, Zl, D_EMB, D_EMB, 0, 0, 0);
    }
    {
        dim3 g(N_SEQ / 256, N_SEQ / 128, N_BATCH);
        gemm_mma<3, 0, false, false><<<g, 256, SMEM_BYTES>>>(
            Zh, Zl, xh, xl, nullptr, S, nullptr, nullptr, N_SEQ, D_EMB,
            (long long)N_SEQ * D_EMB, (long long)N_SEQ * D_EMB,
            (long long)N_SEQ * N_SEQ);
    }

    // join: softmax needs w (side stream), T needs Vth (side stream)
    cudaStreamWaitEvent(0, g_eW, 0);
    softmax_split<<<BN_TOT, 256>>>(S, w, ah);

    cudaStreamWaitEvent(0, g_eV, 0);
    {
        dim3 g(D_EMB / 256, N_SEQ / 128, N_BATCH);
        gemm_mma<1, 2, false, false><<<g, 256, SMEM_BYTES>>>(
            ah, nullptr, Vth, nullptr, nullptr, nullptr, Th, nullptr, D_EMB, N_SEQ,
            (long long)N_SEQ * N_SEQ, (long long)D_EMB * N_SEQ,
            (long long)N_SEQ * D_EMB);
    }
    {
        dim3 g(D_EMB / 256, BN_TOT / 128, 1);
        gemm_mma<1, 0, true, true><<<g, 256, SMEM_BYTES>>>(
            Th, nullptr, Wmh, nullptr, bm, out, nullptr, nullptr, D_EMB, D_EMB, 0, 0, 0);
    }
}